// round 1
// baseline (speedup 1.0000x reference)
#include <cuda_runtime.h>
#include <math.h>

// ---------------------------------------------------------------------------
// GridMambaBlock: B=4, C=64, T=128, F=128
// D_INNER=128, NHEADS=2, HEADDIM=64, D_STATE=64, CONV_DIM=256, D_IN_PROJ=386
// Tokens per stage: 512 seqs x 128 positions = 65536, 64 channels.
// ---------------------------------------------------------------------------

#define TOK      65536
#define NSEQ     512
#define LSEQ     128
#define DMODEL   64
#define DINNER   128
#define NHEADS   2
#define HEADDIM  64
#define DSTATE   64
#define CONVDIM  256
#define DPROJ    386
#define EPS      1e-5f

// Scratch (device globals; allocation-free at runtime)
__device__ float g_u[TOK * DMODEL];                // layernormed input
__device__ float g_zx[2][TOK * DPROJ];             // zxbcdt per direction (original order)
__device__ float g_xbc[2][TOK * CONVDIM];          // conv+silu output (direction order)
__device__ float g_dt[2][TOK * NHEADS];            // softplus dt (direction order)
__device__ float g_dA[2][TOK * NHEADS];            // exp(-exp(A)*dt) (direction order)
__device__ float g_y[2][TOK * DINNER];             // scan output -> gated/normed (original order)
__device__ float g_cat[TOK * 2 * DMODEL];          // [out_f | out_b]
__device__ float g_fused[TOK * DMODEL];            // fusion output

// ---------------------------------------------------------------------------
// Generic SGEMM: C[M,N] = A[M,K] @ W[N,K]^T (+bias), row-major, ldc/col-offset
// 64x64 tile, BK=16, 256 threads, 4x4 per thread. K must be multiple of 16.
// ---------------------------------------------------------------------------
__global__ void sgemm_tn(const float* __restrict__ A, const float* __restrict__ W,
                         const float* __restrict__ bias, float* __restrict__ C,
                         int M, int N, int K, int ldc, int coff)
{
    __shared__ float As[16][65];
    __shared__ float Ws[16][65];
    const int tid = threadIdx.x;
    const int bm = blockIdx.y * 64, bn = blockIdx.x * 64;
    const int tx = tid & 15, ty = tid >> 4;

    float acc[4][4];
#pragma unroll
    for (int i = 0; i < 4; i++)
#pragma unroll
        for (int j = 0; j < 4; j++) acc[i][j] = 0.f;

    for (int k0 = 0; k0 < K; k0 += 16) {
#pragma unroll
        for (int i = 0; i < 4; i++) {
            int idx = tid + i * 256;          // 0..1023
            int m = idx >> 4, k = idx & 15;
            int gm = bm + m, gn = bn + m, gk = k0 + k;
            As[k][m] = (gm < M) ? A[(size_t)gm * K + gk] : 0.f;
            Ws[k][m] = (gn < N) ? W[(size_t)gn * K + gk] : 0.f;
        }
        __syncthreads();
#pragma unroll
        for (int k = 0; k < 16; k++) {
            float a[4], w[4];
#pragma unroll
            for (int i = 0; i < 4; i++) a[i] = As[k][ty * 4 + i];
#pragma unroll
            for (int j = 0; j < 4; j++) w[j] = Ws[k][tx * 4 + j];
#pragma unroll
            for (int i = 0; i < 4; i++)
#pragma unroll
                for (int j = 0; j < 4; j++) acc[i][j] += a[i] * w[j];
        }
        __syncthreads();
    }

#pragma unroll
    for (int i = 0; i < 4; i++) {
        int gm = bm + ty * 4 + i;
        if (gm >= M) continue;
#pragma unroll
        for (int j = 0; j < 4; j++) {
            int gn = bn + tx * 4 + j;
            if (gn >= N) continue;
            float v = acc[i][j];
            if (bias) v += bias[gn];
            C[(size_t)gm * ldc + coff + gn] = v;
        }
    }
}

// ---------------------------------------------------------------------------
// LayerNorm over C=64 of the permuted residual. One warp per token.
// stage0: token=(b*T+t)*F+f -> x[b,c,t,f];  stage1: token=(b*F+f)*T+t
// ---------------------------------------------------------------------------
__global__ void ln_kernel(const float* __restrict__ x, const float* __restrict__ lnw,
                          const float* __restrict__ lnb, float* __restrict__ u, int stage)
{
    int warp = threadIdx.x >> 5, lane = threadIdx.x & 31;
    int token = blockIdx.x * 4 + warp;             // grid 16384, block 128
    int seq = token >> 7, pos = token & 127;
    int b = seq >> 7, s2 = seq & 127;
    int t = (stage == 0) ? s2 : pos;
    int f = (stage == 0) ? pos : s2;
    const float* xb = x + ((size_t)(b * DMODEL) * LSEQ + t) * LSEQ + f;
    float v0 = xb[(size_t)lane * 16384];
    float v1 = xb[(size_t)(lane + 32) * 16384];

    float s = v0 + v1;
#pragma unroll
    for (int off = 16; off; off >>= 1) s += __shfl_xor_sync(0xffffffffu, s, off);
    float mean = s * (1.f / 64.f);
    float d0 = v0 - mean, d1 = v1 - mean;
    float vs = d0 * d0 + d1 * d1;
#pragma unroll
    for (int off = 16; off; off >>= 1) vs += __shfl_xor_sync(0xffffffffu, vs, off);
    float rstd = rsqrtf(vs * (1.f / 64.f) + EPS);

    float* ur = u + (size_t)token * DMODEL;
    ur[lane]      = d0 * rstd * lnw[lane]      + lnb[lane];
    ur[lane + 32] = d1 * rstd * lnw[lane + 32] + lnb[lane + 32];
}

// ---------------------------------------------------------------------------
// Depthwise causal conv (k=4) + bias + SiLU over the xBC slice of zxbcdt.
// Output in DIRECTION order; input read at original index (dir reversal).
// grid 512 seqs, block 256 (one thread per channel j).
// ---------------------------------------------------------------------------
__global__ void conv_kernel(const float* __restrict__ zx, const float* __restrict__ cw,
                            const float* __restrict__ cb, float* __restrict__ out, int dir)
{
    int seq = blockIdx.x;
    int j = threadIdx.x;
    float w0 = cw[j * 4 + 0], w1 = cw[j * 4 + 1], w2 = cw[j * 4 + 2], w3 = cw[j * 4 + 3];
    float b = cb[j];
    const float* base = zx + (size_t)seq * LSEQ * DPROJ + DINNER + j;
    float* obase = out + (size_t)seq * LSEQ * CONVDIM + j;
    float x0 = 0.f, x1 = 0.f, x2 = 0.f;
    for (int l = 0; l < LSEQ; l++) {
        int orig = dir ? (LSEQ - 1 - l) : l;
        float x3 = base[(size_t)orig * DPROJ];
        float v = w0 * x0 + w1 * x1 + w2 * x2 + w3 * x3 + b;
        v = v / (1.f + expf(-v));     // silu
        obase[(size_t)l * CONVDIM] = v;
        x0 = x1; x1 = x2; x2 = x3;
    }
}

// ---------------------------------------------------------------------------
// dt = softplus(zx[...,384+h] + dt_bias); dA = exp(-exp(A_log)*dt)
// Direction order. grid 512, block 128 (thread = position l).
// ---------------------------------------------------------------------------
__global__ void dt_kernel(const float* __restrict__ zx, const float* __restrict__ dtb,
                          const float* __restrict__ Al, float* __restrict__ dtout,
                          float* __restrict__ dAout, int dir)
{
    int seq = blockIdx.x;
    int l = threadIdx.x;
    int orig = dir ? (LSEQ - 1 - l) : l;
    const float* row = zx + ((size_t)seq * LSEQ + orig) * DPROJ + (DPROJ - NHEADS);
#pragma unroll
    for (int h = 0; h < NHEADS; h++) {
        float raw = row[h] + dtb[h];
        float dt = (raw > 20.f) ? raw : log1pf(expf(raw));
        float dA = expf(-expf(Al[h]) * dt);
        size_t idx = ((size_t)seq * LSEQ + l) * NHEADS + h;
        dtout[idx] = dt;
        dAout[idx] = dA;
    }
}

// ---------------------------------------------------------------------------
// Selective scan. One block per seq; 128 threads = 2 heads x 64 p.
// State h[p][0..63] in registers. Writes y+D*x in ORIGINAL order.
// ---------------------------------------------------------------------------
__global__ void scan_kernel(const float* __restrict__ xbc, const float* __restrict__ dtb,
                            const float* __restrict__ dAb, const float* __restrict__ Dp,
                            float* __restrict__ ybuf, int dir)
{
    int seq = blockIdx.x;
    int tid = threadIdx.x;
    int h = tid >> 6;
    __shared__ float Bsh[64];
    __shared__ float Csh[64];

    float hs[64];
#pragma unroll
    for (int n = 0; n < 64; n++) hs[n] = 0.f;
    const float Dh = Dp[h];
    const float* xrow = xbc + (size_t)seq * LSEQ * CONVDIM;
    const float* dtrow = dtb + (size_t)seq * LSEQ * NHEADS;
    const float* darow = dAb + (size_t)seq * LSEQ * NHEADS;
    float* yrow = ybuf + (size_t)seq * LSEQ * DINNER;

    for (int l = 0; l < LSEQ; l++) {
        const float* r = xrow + (size_t)l * CONVDIM;
        if (tid < 64) Bsh[tid] = r[DINNER + tid];
        else          Csh[tid - 64] = r[DINNER + DSTATE + (tid - 64)];
        float xp = r[tid];                       // channel h*64+p == tid
        float dt = dtrow[l * NHEADS + h];
        float dA = darow[l * NHEADS + h];
        __syncthreads();

        float coef = dt * xp;
        float y = 0.f;
        const float4* B4 = (const float4*)Bsh;
        const float4* C4 = (const float4*)Csh;
#pragma unroll
        for (int n4 = 0; n4 < 16; n4++) {
            float4 bb = B4[n4];
            float4 cc = C4[n4];
            int n = n4 * 4;
            hs[n + 0] = hs[n + 0] * dA + coef * bb.x;  y += hs[n + 0] * cc.x;
            hs[n + 1] = hs[n + 1] * dA + coef * bb.y;  y += hs[n + 1] * cc.y;
            hs[n + 2] = hs[n + 2] * dA + coef * bb.z;  y += hs[n + 2] * cc.z;
            hs[n + 3] = hs[n + 3] * dA + coef * bb.w;  y += hs[n + 3] * cc.w;
        }
        int orig = dir ? (LSEQ - 1 - l) : l;
        yrow[(size_t)orig * DINNER + tid] = y + Dh * xp;
        __syncthreads();
    }
}

// ---------------------------------------------------------------------------
// g = y * silu(z); RMSNorm over 128 ch; * norm_w. In-place on y.
// grid 65536 tokens, block 128.
// ---------------------------------------------------------------------------
__global__ void gate_kernel(const float* __restrict__ zx, const float* __restrict__ nw,
                            float* __restrict__ y)
{
    int token = blockIdx.x;
    int c = threadIdx.x;
    int warp = c >> 5, lane = c & 31;
    __shared__ float red[4];

    float z = zx[(size_t)token * DPROJ + c];
    float yv = y[(size_t)token * DINNER + c];
    float g = yv * (z / (1.f + expf(-z)));

    float s = g * g;
#pragma unroll
    for (int off = 16; off; off >>= 1) s += __shfl_xor_sync(0xffffffffu, s, off);
    if (lane == 0) red[warp] = s;
    __syncthreads();
    float tot = red[0] + red[1] + red[2] + red[3];
    float r = rsqrtf(tot * (1.f / 128.f) + EPS);
    y[(size_t)token * DINNER + c] = g * r * nw[c];
}

// ---------------------------------------------------------------------------
// Residual add back into x (B,C,T,F) with stage permutation.
// ---------------------------------------------------------------------------
__global__ void resadd_kernel(float* __restrict__ x, const float* __restrict__ fused, int stage)
{
    int i = blockIdx.x * blockDim.x + threadIdx.x;   // 4.19M elements
    int f = i & 127, t = (i >> 7) & 127, c = (i >> 14) & 63, b = i >> 20;
    int token = (stage == 0) ? ((b * LSEQ + t) * LSEQ + f)
                             : ((b * LSEQ + f) * LSEQ + t);
    x[i] += fused[(size_t)token * DMODEL + c];
}

// ---------------------------------------------------------------------------
// Launch
// ---------------------------------------------------------------------------
extern "C" void kernel_launch(void* const* d_in, const int* in_sizes, int n_in,
                              void* d_out, int out_size)
{
    const float* x_in     = (const float*)d_in[0];
    const float* in_projW = (const float*)d_in[1];   // (4, 386, 64)
    const float* convW    = (const float*)d_in[2];   // (4, 256, 4)
    const float* convB    = (const float*)d_in[3];   // (4, 256)
    const float* dt_bias  = (const float*)d_in[4];   // (4, 2)
    const float* A_log    = (const float*)d_in[5];   // (4, 2)
    const float* D_param  = (const float*)d_in[6];   // (4, 2)
    const float* norm_w   = (const float*)d_in[7];   // (4, 128)
    const float* out_W    = (const float*)d_in[8];   // (4, 64, 128)
    const float* fusion_W = (const float*)d_in[9];   // (2, 64, 128)
    const float* fusion_b = (const float*)d_in[10];  // (2, 64)
    const float* ln_w     = (const float*)d_in[11];  // (2, 64)
    const float* ln_b     = (const float*)d_in[12];  // (2, 64)
    float* xo = (float*)d_out;                       // (4, 64, 128, 128) residual

    // residual init
    cudaMemcpyAsync(xo, x_in, (size_t)TOK * DMODEL * sizeof(float),
                    cudaMemcpyDeviceToDevice);

    float *p_u, *p_cat, *p_fused;
    float *p_zx[2], *p_xbc[2], *p_dt[2], *p_dA[2], *p_y[2];
    cudaGetSymbolAddress((void**)&p_u, g_u);
    cudaGetSymbolAddress((void**)&p_cat, g_cat);
    cudaGetSymbolAddress((void**)&p_fused, g_fused);
    {
        float* tmp;
        cudaGetSymbolAddress((void**)&tmp, g_zx);  p_zx[0]  = tmp; p_zx[1]  = tmp + (size_t)TOK * DPROJ;
        cudaGetSymbolAddress((void**)&tmp, g_xbc); p_xbc[0] = tmp; p_xbc[1] = tmp + (size_t)TOK * CONVDIM;
        cudaGetSymbolAddress((void**)&tmp, g_dt);  p_dt[0]  = tmp; p_dt[1]  = tmp + (size_t)TOK * NHEADS;
        cudaGetSymbolAddress((void**)&tmp, g_dA);  p_dA[0]  = tmp; p_dA[1]  = tmp + (size_t)TOK * NHEADS;
        cudaGetSymbolAddress((void**)&tmp, g_y);   p_y[0]   = tmp; p_y[1]   = tmp + (size_t)TOK * DINNER;
    }

    for (int s = 0; s < 2; s++) {
        // LayerNorm -> u
        ln_kernel<<<TOK / 4, 128>>>(xo, ln_w + s * DMODEL, ln_b + s * DMODEL, p_u, s);

        for (int d = 0; d < 2; d++) {
            int pi = 2 * s + d;
            // in_proj: u (65536x64) @ Wp^T (386x64) -> zx
            {
                dim3 grid((DPROJ + 63) / 64, TOK / 64);
                sgemm_tn<<<grid, 256>>>(p_u, in_projW + (size_t)pi * DPROJ * DMODEL,
                                        nullptr, p_zx[d], TOK, DPROJ, DMODEL, DPROJ, 0);
            }
            conv_kernel<<<NSEQ, CONVDIM>>>(p_zx[d], convW + (size_t)pi * CONVDIM * 4,
                                           convB + (size_t)pi * CONVDIM, p_xbc[d], d);
            dt_kernel<<<NSEQ, LSEQ>>>(p_zx[d], dt_bias + pi * NHEADS, A_log + pi * NHEADS,
                                      p_dt[d], p_dA[d], d);
            scan_kernel<<<NSEQ, DINNER>>>(p_xbc[d], p_dt[d], p_dA[d],
                                          D_param + pi * NHEADS, p_y[d], d);
            gate_kernel<<<TOK, DINNER>>>(p_zx[d], norm_w + (size_t)pi * DINNER, p_y[d]);
            // out proj: g (65536x128) @ Wo^T (64x128) -> cat[:, d*64:(d+1)*64]
            {
                dim3 grid(1, TOK / 64);
                sgemm_tn<<<grid, 256>>>(p_y[d], out_W + (size_t)pi * DMODEL * DINNER,
                                        nullptr, p_cat, TOK, DMODEL, DINNER,
                                        2 * DMODEL, d * DMODEL);
            }
        }
        // fusion: cat (65536x128) @ fW^T (64x128) + fb -> fused
        {
            dim3 grid(1, TOK / 64);
            sgemm_tn<<<grid, 256>>>(p_cat, fusion_W + (size_t)s * DMODEL * 2 * DMODEL,
                                    fusion_b + s * DMODEL, p_fused,
                                    TOK, DMODEL, 2 * DMODEL, DMODEL, 0);
        }
        resadd_kernel<<<(TOK * DMODEL) / 256, 256>>>(xo, p_fused, s);
    }
}

// round 2
// speedup vs baseline: 2.1162x; 2.1162x over previous
#include <cuda_runtime.h>
#include <mma.h>
#include <math.h>

using namespace nvcuda;

// ---------------------------------------------------------------------------
// GridMambaBlock: B=4, C=64, T=128, F=128
// D_INNER=128, NHEADS=2, HEADDIM=64, D_STATE=64, CONV_DIM=256, D_IN_PROJ=386
// Tokens per stage: 512 seqs x 128 positions = 65536, 64 channels.
// ---------------------------------------------------------------------------

#define TOK      65536
#define NSEQ     512
#define LSEQ     128
#define DMODEL   64
#define DINNER   128
#define NHEADS   2
#define DSTATE   64
#define CONVDIM  256
#define DPROJ    386
#define ZLD      832          // padded row stride for combined zx (2*386=772 -> 13*64)
#define EPS      1e-5f

// Scratch (device globals; allocation-free at runtime)
__device__ float g_u[TOK * DMODEL];          // layernormed input
__device__ float g_zx[(size_t)TOK * ZLD];    // zxbcdt, both dirs in columns
__device__ float g_y[(size_t)TOK * 256];     // gated scan output, both dirs concat
__device__ float g_fused[TOK * DMODEL];      // fusion output
__device__ float g_wcomb[2][64 * 256];       // combined out_proj+fusion weights

// ---------------------------------------------------------------------------
// tf32 wmma GEMM: C[M,N] = A[M,K] @ W[N,K]^T, row-major.
// BM=128, BN=64, BK=32, 256 threads (8 warps, 4x2, each warp 32x32).
// K multiple of 32; M multiple of 128; ldc multiple of 4 and >= padded N tile.
// ---------------------------------------------------------------------------
__global__ __launch_bounds__(256) void gemm_tf32(
    const float* __restrict__ A, const float* __restrict__ W,
    float* __restrict__ C, int M, int N, int K, int ldc)
{
    __shared__ float Asm[128 * 36];
    __shared__ float Wsm[64 * 36];
    const int tid = threadIdx.x;
    const int bm = blockIdx.y * 128, bn = blockIdx.x * 64;
    const int warp = tid >> 5;
    const int wr = (warp >> 1) * 32, wc = (warp & 1) * 32;

    wmma::fragment<wmma::accumulator, 16, 16, 8, float> acc[2][2];
#pragma unroll
    for (int i = 0; i < 2; i++)
#pragma unroll
        for (int j = 0; j < 2; j++) wmma::fill_fragment(acc[i][j], 0.f);

    for (int k0 = 0; k0 < K; k0 += 32) {
        // load A tile 128x32
#pragma unroll
        for (int i = 0; i < 4; i++) {
            int id = tid + i * 256;
            int row = id >> 3, kq = id & 7;
            float4 v = make_float4(0.f, 0.f, 0.f, 0.f);
            int gm = bm + row;
            if (gm < M) v = *(const float4*)(A + (size_t)gm * K + k0 + kq * 4);
            *(float4*)&Asm[row * 36 + kq * 4] = v;
        }
        // load W tile 64x32 (zero-fill OOB rows)
#pragma unroll
        for (int i = 0; i < 2; i++) {
            int id = tid + i * 256;
            int row = id >> 3, kq = id & 7;
            float4 v = make_float4(0.f, 0.f, 0.f, 0.f);
            int gn = bn + row;
            if (gn < N) v = *(const float4*)(W + (size_t)gn * K + k0 + kq * 4);
            *(float4*)&Wsm[row * 36 + kq * 4] = v;
        }
        __syncthreads();

#pragma unroll
        for (int kk = 0; kk < 32; kk += 8) {
            wmma::fragment<wmma::matrix_a, 16, 16, 8, wmma::precision::tf32, wmma::row_major> a0, a1;
            wmma::fragment<wmma::matrix_b, 16, 16, 8, wmma::precision::tf32, wmma::col_major> b0, b1;
            wmma::load_matrix_sync(a0, Asm + (wr)      * 36 + kk, 36);
            wmma::load_matrix_sync(a1, Asm + (wr + 16) * 36 + kk, 36);
            wmma::load_matrix_sync(b0, Wsm + (wc)      * 36 + kk, 36);
            wmma::load_matrix_sync(b1, Wsm + (wc + 16) * 36 + kk, 36);
#pragma unroll
            for (int e = 0; e < a0.num_elements; e++) {
                a0.x[e] = wmma::__float_to_tf32(a0.x[e]);
                a1.x[e] = wmma::__float_to_tf32(a1.x[e]);
            }
#pragma unroll
            for (int e = 0; e < b0.num_elements; e++) {
                b0.x[e] = wmma::__float_to_tf32(b0.x[e]);
                b1.x[e] = wmma::__float_to_tf32(b1.x[e]);
            }
            wmma::mma_sync(acc[0][0], a0, b0, acc[0][0]);
            wmma::mma_sync(acc[0][1], a0, b1, acc[0][1]);
            wmma::mma_sync(acc[1][0], a1, b0, acc[1][0]);
            wmma::mma_sync(acc[1][1], a1, b1, acc[1][1]);
        }
        __syncthreads();
    }

#pragma unroll
    for (int i = 0; i < 2; i++)
#pragma unroll
        for (int j = 0; j < 2; j++)
            wmma::store_matrix_sync(C + (size_t)(bm + wr + i * 16) * ldc + bn + wc + j * 16,
                                    acc[i][j], ldc, wmma::mem_row_major);
}

// ---------------------------------------------------------------------------
// Precompute combined weights: W'[s][n][d*128+c] = sum_j Wf[s][n][d*64+j]*Wo[2s+d][j][c]
// ---------------------------------------------------------------------------
__global__ void wcomb_kernel(const float* __restrict__ outW,
                             const float* __restrict__ fusW,
                             float* __restrict__ wc)
{
    int s = blockIdx.x;
    for (int idx = threadIdx.x; idx < 64 * 256; idx += blockDim.x) {
        int n = idx >> 8, k = idx & 255;
        int d = k >> 7, c = k & 127;
        const float* wf = fusW + (size_t)(s * 64 + n) * 128 + d * 64;
        const float* wo = outW + (size_t)((s * 2 + d) * 64) * 128 + c;
        float acc = 0.f;
#pragma unroll
        for (int j = 0; j < 64; j++) acc += wf[j] * wo[(size_t)j * 128];
        wc[(size_t)s * 64 * 256 + idx] = acc;
    }
}

// ---------------------------------------------------------------------------
// LayerNorm over C=64 of the permuted residual. One warp per token.
// ---------------------------------------------------------------------------
__global__ void ln_kernel(const float* __restrict__ x, const float* __restrict__ lnw,
                          const float* __restrict__ lnb, float* __restrict__ u, int stage)
{
    int warp = threadIdx.x >> 5, lane = threadIdx.x & 31;
    int token = blockIdx.x * 4 + warp;
    int seq = token >> 7, pos = token & 127;
    int b = seq >> 7, s2 = seq & 127;
    int t = (stage == 0) ? s2 : pos;
    int f = (stage == 0) ? pos : s2;
    const float* xb = x + ((size_t)(b * DMODEL) * LSEQ + t) * LSEQ + f;
    float v0 = xb[(size_t)lane * 16384];
    float v1 = xb[(size_t)(lane + 32) * 16384];

    float s = v0 + v1;
#pragma unroll
    for (int off = 16; off; off >>= 1) s += __shfl_xor_sync(0xffffffffu, s, off);
    float mean = s * (1.f / 64.f);
    float d0 = v0 - mean, d1 = v1 - mean;
    float vs = d0 * d0 + d1 * d1;
#pragma unroll
    for (int off = 16; off; off >>= 1) vs += __shfl_xor_sync(0xffffffffu, vs, off);
    float rstd = rsqrtf(vs * (1.f / 64.f) + EPS);

    float* ur = u + (size_t)token * DMODEL;
    ur[lane]      = d0 * rstd * lnw[lane]      + lnb[lane];
    ur[lane + 32] = d1 * rstd * lnw[lane + 32] + lnb[lane + 32];
}

// ---------------------------------------------------------------------------
// Fused conv + dt + selective-scan + gate/RMSnorm.
// grid = 1024 (seq, dir interleaved), block = 128.
// Thread tid: scan channel tid; conv channels tid (x) and 128+tid (B/C).
// Writes gated output into g_y[token][dir*128 + tid] (original token order).
// ---------------------------------------------------------------------------
__global__ __launch_bounds__(128) void fused_scan(
    const float* __restrict__ zx, const float* __restrict__ convW,
    const float* __restrict__ convB, const float* __restrict__ dtb,
    const float* __restrict__ Al, const float* __restrict__ Dp,
    const float* __restrict__ nw, float* __restrict__ ybuf, int pi0)
{
    int blk = blockIdx.x;
    int dir = blk & 1;
    int seq = blk >> 1;
    int pi  = pi0 + dir;
    int tid = threadIdx.x;
    int h = tid >> 6;
    int warp = tid >> 5, lane = tid & 31;

    __shared__ float Bsh[64], Csh[64];
    __shared__ float dts[2], das[2];
    __shared__ float red[4];

    // conv params: channel tid (x part), channel 128+tid (B/C part)
    const float* cw = convW + (size_t)pi * CONVDIM * 4;
    float w10 = cw[tid * 4 + 0], w11 = cw[tid * 4 + 1], w12 = cw[tid * 4 + 2], w13 = cw[tid * 4 + 3];
    float w20 = cw[(128 + tid) * 4 + 0], w21 = cw[(128 + tid) * 4 + 1],
          w22 = cw[(128 + tid) * 4 + 2], w23 = cw[(128 + tid) * 4 + 3];
    float cb1 = convB[pi * CONVDIM + tid];
    float cb2 = convB[pi * CONVDIM + 128 + tid];
    float Dh  = Dp[pi * NHEADS + h];
    float nwv = nw[(size_t)pi * DINNER + tid];
    float Aexp = 0.f, dtbh = 0.f;
    if (tid < 2) { Aexp = expf(Al[pi * NHEADS + tid]); dtbh = dtb[pi * NHEADS + tid]; }

    const float* zrow0 = zx + (size_t)seq * LSEQ * ZLD + dir * DPROJ;
    float* yrow0 = ybuf + (size_t)seq * LSEQ * 256 + dir * 128 + tid;

    float hx0 = 0.f, hx1 = 0.f, hx2 = 0.f;      // conv history, x channel
    float hb0 = 0.f, hb1 = 0.f, hb2 = 0.f;      // conv history, B/C channel
    float hs[64];
#pragma unroll
    for (int n = 0; n < 64; n++) hs[n] = 0.f;

    for (int l = 0; l < LSEQ; l++) {
        int orig = dir ? (LSEQ - 1 - l) : l;
        const float* r = zrow0 + (size_t)orig * ZLD;
        float zval = r[tid];
        float xin  = r[128 + tid];
        float bcin = r[256 + tid];

        // streaming causal conv + silu
        float vx = w10 * hx0 + w11 * hx1 + w12 * hx2 + w13 * xin + cb1;
        vx = vx / (1.f + expf(-vx));
        hx0 = hx1; hx1 = hx2; hx2 = xin;
        float vbc = w20 * hb0 + w21 * hb1 + w22 * hb2 + w23 * bcin + cb2;
        vbc = vbc / (1.f + expf(-vbc));
        hb0 = hb1; hb1 = hb2; hb2 = bcin;

        if (tid < 64) Bsh[tid] = vbc;
        else          Csh[tid - 64] = vbc;

        if (tid < 2) {
            float raw = r[384 + tid] + dtbh;
            float dt = (raw > 20.f) ? raw : log1pf(expf(raw));
            dts[tid] = dt;
            das[tid] = expf(-Aexp * dt);
        }
        __syncthreads();

        float dt = dts[h], dA = das[h];
        float coef = dt * vx;
        float y = 0.f;
        const float4* B4 = (const float4*)Bsh;
        const float4* C4 = (const float4*)Csh;
#pragma unroll
        for (int n4 = 0; n4 < 16; n4++) {
            float4 bb = B4[n4];
            float4 cc = C4[n4];
            int n = n4 * 4;
            hs[n + 0] = hs[n + 0] * dA + coef * bb.x;  y += hs[n + 0] * cc.x;
            hs[n + 1] = hs[n + 1] * dA + coef * bb.y;  y += hs[n + 1] * cc.y;
            hs[n + 2] = hs[n + 2] * dA + coef * bb.z;  y += hs[n + 2] * cc.z;
            hs[n + 3] = hs[n + 3] * dA + coef * bb.w;  y += hs[n + 3] * cc.w;
        }

        // gate + RMSnorm over the 128 channels of this token
        float g = (y + Dh * vx) * (zval / (1.f + expf(-zval)));
        float ss = g * g;
#pragma unroll
        for (int off = 16; off; off >>= 1) ss += __shfl_xor_sync(0xffffffffu, ss, off);
        if (lane == 0) red[warp] = ss;
        __syncthreads();
        float tot = red[0] + red[1] + red[2] + red[3];
        float rinv = rsqrtf(tot * (1.f / 128.f) + EPS);
        yrow0[(size_t)orig * 256] = g * rinv * nwv;
    }
}

// ---------------------------------------------------------------------------
// Residual add (+fusion bias) back into x (B,C,T,F) with stage permutation.
// ---------------------------------------------------------------------------
__global__ void resadd_kernel(float* __restrict__ x, const float* __restrict__ fused,
                              const float* __restrict__ fb, int stage)
{
    int i = blockIdx.x * blockDim.x + threadIdx.x;
    int f = i & 127, t = (i >> 7) & 127, c = (i >> 14) & 63, b = i >> 20;
    int token = (stage == 0) ? ((b * LSEQ + t) * LSEQ + f)
                             : ((b * LSEQ + f) * LSEQ + t);
    x[i] += fused[(size_t)token * DMODEL + c] + fb[c];
}

// ---------------------------------------------------------------------------
// Launch
// ---------------------------------------------------------------------------
extern "C" void kernel_launch(void* const* d_in, const int* in_sizes, int n_in,
                              void* d_out, int out_size)
{
    const float* x_in     = (const float*)d_in[0];
    const float* in_projW = (const float*)d_in[1];   // (4, 386, 64)
    const float* convW    = (const float*)d_in[2];   // (4, 256, 4)
    const float* convB    = (const float*)d_in[3];   // (4, 256)
    const float* dt_bias  = (const float*)d_in[4];   // (4, 2)
    const float* A_log    = (const float*)d_in[5];   // (4, 2)
    const float* D_param  = (const float*)d_in[6];   // (4, 2)
    const float* norm_w   = (const float*)d_in[7];   // (4, 128)
    const float* out_W    = (const float*)d_in[8];   // (4, 64, 128)
    const float* fusion_W = (const float*)d_in[9];   // (2, 64, 128)
    const float* fusion_b = (const float*)d_in[10];  // (2, 64)
    const float* ln_w     = (const float*)d_in[11];  // (2, 64)
    const float* ln_b     = (const float*)d_in[12];  // (2, 64)
    float* xo = (float*)d_out;                       // (4, 64, 128, 128) residual

    cudaMemcpyAsync(xo, x_in, (size_t)TOK * DMODEL * sizeof(float),
                    cudaMemcpyDeviceToDevice);

    float *p_u, *p_zx, *p_y, *p_fused, *p_wcomb;
    cudaGetSymbolAddress((void**)&p_u, g_u);
    cudaGetSymbolAddress((void**)&p_zx, g_zx);
    cudaGetSymbolAddress((void**)&p_y, g_y);
    cudaGetSymbolAddress((void**)&p_fused, g_fused);
    cudaGetSymbolAddress((void**)&p_wcomb, g_wcomb);

    // combined out_proj+fusion weights (both stages)
    wcomb_kernel<<<2, 256>>>(out_W, fusion_W, p_wcomb);

    for (int s = 0; s < 2; s++) {
        ln_kernel<<<TOK / 4, 128>>>(xo, ln_w + s * DMODEL, ln_b + s * DMODEL, p_u, s);

        // combined in_proj for both directions: u (65536x64) @ [Wp_2s;Wp_2s+1]^T
        {
            dim3 grid(13, TOK / 128);
            gemm_tf32<<<grid, 256>>>(p_u, in_projW + (size_t)(2 * s) * DPROJ * DMODEL,
                                     p_zx, TOK, 2 * DPROJ, DMODEL, ZLD);
        }

        // fused conv+dt+scan+gate, both directions
        fused_scan<<<2 * NSEQ, 128>>>(p_zx, convW, convB, dt_bias, A_log, D_param,
                                      norm_w, p_y, 2 * s);

        // combined out_proj + fusion GEMM: y (65536x256) @ Wcomb[s]^T (64x256)
        {
            dim3 grid(1, TOK / 128);
            gemm_tf32<<<grid, 256>>>(p_y, p_wcomb + (size_t)s * 64 * 256,
                                     p_fused, TOK, DMODEL, 256, DMODEL);
        }

        resadd_kernel<<<(TOK * DMODEL) / 256, 256>>>(xo, p_fused, fusion_b + s * DMODEL, s);
    }
}

// round 3
// speedup vs baseline: 2.1928x; 1.0362x over previous
#include <cuda_runtime.h>
#include <mma.h>
#include <math.h>

using namespace nvcuda;

// ---------------------------------------------------------------------------
// GridMambaBlock: B=4, C=64, T=128, F=128
// D_INNER=128, NHEADS=2, HEADDIM=64, D_STATE=64, CONV_DIM=256, D_IN_PROJ=386
// ---------------------------------------------------------------------------

#define TOK      65536
#define NSEQ     512
#define LSEQ     128
#define DMODEL   64
#define DINNER   128
#define NHEADS   2
#define CONVDIM  256
#define DPROJ    386
#define ZLD      832          // padded row stride for combined zx (2*386=772 -> 13*64)
#define EPS      1e-5f

// SSD shared-memory pool offsets (floats)
#define SB_OFF   0            // B tile, stride 68, 128 rows   (later Y head0)
#define SC_OFF   8704         // C tile, stride 68             (later Y head1)
#define SG_OFF   17408        // G 128x128, stride 132
#define SM_OFF   34304        // M slab 128x16, stride 20
#define SX_OFF   36864        // X 128x128 (both heads), stride 136
#define SSD_SMEM ((36864 + 17408) * 4)   // 217088 bytes

// Scratch (device globals; allocation-free at runtime)
__device__ float g_u[TOK * DMODEL];          // layernormed input
__device__ float g_zx[(size_t)TOK * ZLD];    // zxbcdt, both dirs in columns
__device__ float g_y[(size_t)TOK * 256];     // gated scan output, both dirs concat
__device__ float g_fused[TOK * DMODEL];      // fusion output
__device__ float g_wcomb[2][64 * 256];       // combined out_proj+fusion weights

// ---------------------------------------------------------------------------
// tf32 wmma GEMM: C[M,N] = A[M,K] @ W[N,K]^T, row-major.
// BM=128, BN=64, BK=32, 256 threads. ldc >= padded tile, M%128==0, K%32==0.
// ---------------------------------------------------------------------------
__global__ __launch_bounds__(256) void gemm_tf32(
    const float* __restrict__ A, const float* __restrict__ W,
    float* __restrict__ C, int M, int N, int K, int ldc)
{
    __shared__ float Asm[128 * 36];
    __shared__ float Wsm[64 * 36];
    const int tid = threadIdx.x;
    const int bm = blockIdx.y * 128, bn = blockIdx.x * 64;
    const int warp = tid >> 5;
    const int wr = (warp >> 1) * 32, wc = (warp & 1) * 32;

    wmma::fragment<wmma::accumulator, 16, 16, 8, float> acc[2][2];
#pragma unroll
    for (int i = 0; i < 2; i++)
#pragma unroll
        for (int j = 0; j < 2; j++) wmma::fill_fragment(acc[i][j], 0.f);

    for (int k0 = 0; k0 < K; k0 += 32) {
#pragma unroll
        for (int i = 0; i < 4; i++) {
            int id = tid + i * 256;
            int row = id >> 3, kq = id & 7;
            float4 v = make_float4(0.f, 0.f, 0.f, 0.f);
            int gm = bm + row;
            if (gm < M) v = *(const float4*)(A + (size_t)gm * K + k0 + kq * 4);
            *(float4*)&Asm[row * 36 + kq * 4] = v;
        }
#pragma unroll
        for (int i = 0; i < 2; i++) {
            int id = tid + i * 256;
            int row = id >> 3, kq = id & 7;
            float4 v = make_float4(0.f, 0.f, 0.f, 0.f);
            int gn = bn + row;
            if (gn < N) v = *(const float4*)(W + (size_t)gn * K + k0 + kq * 4);
            *(float4*)&Wsm[row * 36 + kq * 4] = v;
        }
        __syncthreads();

#pragma unroll
        for (int kk = 0; kk < 32; kk += 8) {
            wmma::fragment<wmma::matrix_a, 16, 16, 8, wmma::precision::tf32, wmma::row_major> a0, a1;
            wmma::fragment<wmma::matrix_b, 16, 16, 8, wmma::precision::tf32, wmma::col_major> b0, b1;
            wmma::load_matrix_sync(a0, Asm + (wr)      * 36 + kk, 36);
            wmma::load_matrix_sync(a1, Asm + (wr + 16) * 36 + kk, 36);
            wmma::load_matrix_sync(b0, Wsm + (wc)      * 36 + kk, 36);
            wmma::load_matrix_sync(b1, Wsm + (wc + 16) * 36 + kk, 36);
#pragma unroll
            for (int e = 0; e < a0.num_elements; e++) {
                a0.x[e] = wmma::__float_to_tf32(a0.x[e]);
                a1.x[e] = wmma::__float_to_tf32(a1.x[e]);
            }
#pragma unroll
            for (int e = 0; e < b0.num_elements; e++) {
                b0.x[e] = wmma::__float_to_tf32(b0.x[e]);
                b1.x[e] = wmma::__float_to_tf32(b1.x[e]);
            }
            wmma::mma_sync(acc[0][0], a0, b0, acc[0][0]);
            wmma::mma_sync(acc[0][1], a0, b1, acc[0][1]);
            wmma::mma_sync(acc[1][0], a1, b0, acc[1][0]);
            wmma::mma_sync(acc[1][1], a1, b1, acc[1][1]);
        }
        __syncthreads();
    }

#pragma unroll
    for (int i = 0; i < 2; i++)
#pragma unroll
        for (int j = 0; j < 2; j++)
            wmma::store_matrix_sync(C + (size_t)(bm + wr + i * 16) * ldc + bn + wc + j * 16,
                                    acc[i][j], ldc, wmma::mem_row_major);
}

// ---------------------------------------------------------------------------
// Precompute combined weights: W'[s][n][d*128+c] = sum_j Wf[s][n][d*64+j]*Wo[2s+d][j][c]
// ---------------------------------------------------------------------------
__global__ void wcomb_kernel(const float* __restrict__ outW,
                             const float* __restrict__ fusW,
                             float* __restrict__ wc)
{
    int s = blockIdx.x;
    for (int idx = threadIdx.x; idx < 64 * 256; idx += blockDim.x) {
        int n = idx >> 8, k = idx & 255;
        int d = k >> 7, c = k & 127;
        const float* wf = fusW + (size_t)(s * 64 + n) * 128 + d * 64;
        const float* wo = outW + (size_t)((s * 2 + d) * 64) * 128 + c;
        float acc = 0.f;
#pragma unroll
        for (int j = 0; j < 64; j++) acc += wf[j] * wo[(size_t)j * 128];
        wc[(size_t)s * 64 * 256 + idx] = acc;
    }
}

// ---------------------------------------------------------------------------
// LayerNorm over C=64 of the permuted residual. One warp per token.
// ---------------------------------------------------------------------------
__global__ void ln_kernel(const float* __restrict__ x, const float* __restrict__ lnw,
                          const float* __restrict__ lnb, float* __restrict__ u, int stage)
{
    int warp = threadIdx.x >> 5, lane = threadIdx.x & 31;
    int token = blockIdx.x * 4 + warp;
    int seq = token >> 7, pos = token & 127;
    int b = seq >> 7, s2 = seq & 127;
    int t = (stage == 0) ? s2 : pos;
    int f = (stage == 0) ? pos : s2;
    const float* xb = x + ((size_t)(b * DMODEL) * LSEQ + t) * LSEQ + f;
    float v0 = xb[(size_t)lane * 16384];
    float v1 = xb[(size_t)(lane + 32) * 16384];

    float s = v0 + v1;
#pragma unroll
    for (int off = 16; off; off >>= 1) s += __shfl_xor_sync(0xffffffffu, s, off);
    float mean = s * (1.f / 64.f);
    float d0 = v0 - mean, d1 = v1 - mean;
    float vs = d0 * d0 + d1 * d1;
#pragma unroll
    for (int off = 16; off; off >>= 1) vs += __shfl_xor_sync(0xffffffffu, vs, off);
    float rstd = rsqrtf(vs * (1.f / 64.f) + EPS);

    float* ur = u + (size_t)token * DMODEL;
    ur[lane]      = d0 * rstd * lnw[lane]      + lnb[lane];
    ur[lane + 32] = d1 * rstd * lnw[lane + 32] + lnb[lane + 32];
}

// ---------------------------------------------------------------------------
// SSD mega-kernel: conv+silu -> dt/S warp scan -> G=C@B^T (wmma tf32)
// -> per-head masked-decay M slabs @ X (wmma) -> gate + RMSnorm.
// One block per (seq, dir). 512 threads. 217KB dynamic smem.
// y_t = Y_t + D*x_t ; Y = (G .* exp(S[s]-S[t]) .* dt[s], s<=t) @ X
// ---------------------------------------------------------------------------
__global__ __launch_bounds__(512) void ssd_kernel(
    const float* __restrict__ zx, const float* __restrict__ convW,
    const float* __restrict__ convB, const float* __restrict__ dtb,
    const float* __restrict__ Al, const float* __restrict__ Dp,
    const float* __restrict__ nw, float* __restrict__ ybuf, int pi0)
{
    extern __shared__ float sm[];
    __shared__ float Ssm[2][128];
    __shared__ float dtsm[2][128];

    const int blk = blockIdx.x;
    const int dir = blk & 1;
    const int seq = blk >> 1;
    const int pi  = pi0 + dir;
    const int tid = threadIdx.x;
    const int warp = tid >> 5, lane = tid & 31;

    const float* zbase = zx + (size_t)seq * LSEQ * ZLD + dir * DPROJ;

    // ---- Phase 1: streaming causal conv (k=4) + SiLU into smem tiles ----
    {
        int c = tid & 255;            // xBC channel
        int half = tid >> 8;          // 0: l 0..63, 1: l 64..127
        int l0 = half * 64;
        const float4 w4 = *(const float4*)(convW + ((size_t)pi * CONVDIM + c) * 4);
        const float b = convB[pi * CONVDIM + c];
        const float* src = zbase + 128 + c;

        float h0 = 0.f, h1 = 0.f, h2 = 0.f;
        if (half) {
            int o1 = dir ? (127 - 61) : 61;
            int o2 = dir ? (127 - 62) : 62;
            int o3 = dir ? (127 - 63) : 63;
            h0 = src[(size_t)o1 * ZLD];
            h1 = src[(size_t)o2 * ZLD];
            h2 = src[(size_t)o3 * ZLD];
        }
        float* dst;
        int dstride;
        if (c < 128)      { dst = sm + SX_OFF + c;         dstride = 136; }
        else if (c < 192) { dst = sm + SB_OFF + (c - 128); dstride = 68; }
        else              { dst = sm + SC_OFF + (c - 192); dstride = 68; }

        for (int l = l0; l < l0 + 64; l++) {
            int orig = dir ? (127 - l) : l;
            float xin = src[(size_t)orig * ZLD];
            float v = w4.x * h0 + w4.y * h1 + w4.z * h2 + w4.w * xin + b;
            v = v / (1.f + __expf(-v));
            dst[l * dstride] = v;
            h0 = h1; h1 = h2; h2 = xin;
        }
    }

    // ---- Phase 2: dt softplus + cumsum S (warps 0,1 = heads 0,1) ----
    if (warp < 2) {
        int h = warp;
        float aexp = __expf(Al[pi * NHEADS + h]);
        float dtbh = dtb[pi * NHEADS + h];
        float dtv[4], csum[4];
        float run = 0.f;
#pragma unroll
        for (int k = 0; k < 4; k++) {
            int l = lane * 4 + k;
            int orig = dir ? (127 - l) : l;
            float raw = zbase[(size_t)orig * ZLD + 384 + h] + dtbh;
            float dt = (raw > 20.f) ? raw : log1pf(__expf(raw));
            run += aexp * dt;
            dtv[k] = dt; csum[k] = run;
        }
        float tot = run, scan = run;
#pragma unroll
        for (int off = 1; off < 32; off <<= 1) {
            float v = __shfl_up_sync(0xffffffffu, scan, off);
            if (lane >= off) scan += v;
        }
        float prefix = scan - tot;
#pragma unroll
        for (int k = 0; k < 4; k++) {
            int l = lane * 4 + k;
            Ssm[h][l] = prefix + csum[k];
            dtsm[h][l] = dtv[k];
        }
    }
    __syncthreads();

    // ---- Phase 3: G = C @ B^T (128x128x64), 16 warps 4x4, warp tile 32x32 ----
    {
        const int wt = warp >> 2, ws = warp & 3;
        wmma::fragment<wmma::accumulator, 16, 16, 8, float> accG[2][2];
#pragma unroll
        for (int i = 0; i < 2; i++)
#pragma unroll
            for (int j = 0; j < 2; j++) wmma::fill_fragment(accG[i][j], 0.f);

#pragma unroll
        for (int k0 = 0; k0 < 64; k0 += 8) {
            wmma::fragment<wmma::matrix_a, 16, 16, 8, wmma::precision::tf32, wmma::row_major> a[2];
            wmma::fragment<wmma::matrix_b, 16, 16, 8, wmma::precision::tf32, wmma::col_major> bfr[2];
#pragma unroll
            for (int i = 0; i < 2; i++) {
                wmma::load_matrix_sync(a[i], sm + SC_OFF + (wt * 32 + i * 16) * 68 + k0, 68);
#pragma unroll
                for (int e = 0; e < a[i].num_elements; e++) a[i].x[e] = wmma::__float_to_tf32(a[i].x[e]);
            }
#pragma unroll
            for (int j = 0; j < 2; j++) {
                wmma::load_matrix_sync(bfr[j], sm + SB_OFF + (ws * 32 + j * 16) * 68 + k0, 68);
#pragma unroll
                for (int e = 0; e < bfr[j].num_elements; e++) bfr[j].x[e] = wmma::__float_to_tf32(bfr[j].x[e]);
            }
#pragma unroll
            for (int i = 0; i < 2; i++)
#pragma unroll
                for (int j = 0; j < 2; j++) wmma::mma_sync(accG[i][j], a[i], bfr[j], accG[i][j]);
        }
#pragma unroll
        for (int i = 0; i < 2; i++)
#pragma unroll
            for (int j = 0; j < 2; j++)
                wmma::store_matrix_sync(sm + SG_OFF + (wt * 32 + i * 16) * 132 + ws * 32 + j * 16,
                                        accG[i][j], 132, wmma::mem_row_major);
    }
    __syncthreads();   // G visible; B/C now dead (pool becomes Y)

    // ---- Phase 4: per head, masked-decay M slabs @ X -> Y ----
    const int wr = warp >> 1;   // 0..7 : t tile of 16
    const int wc = warp & 1;    // 0..1 : p tile of 32
#pragma unroll
    for (int h = 0; h < 2; h++) {
        wmma::fragment<wmma::accumulator, 16, 16, 8, float> accY[2];
        wmma::fill_fragment(accY[0], 0.f);
        wmma::fill_fragment(accY[1], 0.f);

        for (int slab = 0; slab < 8; slab++) {
            int s0 = slab * 16;
            // build M slab [128 x 16]
#pragma unroll
            for (int i = 0; i < 4; i++) {
                int e = tid + i * 512;
                int t = e >> 4, sl = e & 15;
                int s = s0 + sl;
                float m = 0.f;
                if (s <= t)
                    m = sm[SG_OFF + t * 132 + s] * __expf(Ssm[h][s] - Ssm[h][t]) * dtsm[h][s];
                sm[SM_OFF + t * 20 + sl] = m;
            }
            __syncthreads();
#pragma unroll
            for (int kk = 0; kk < 16; kk += 8) {
                wmma::fragment<wmma::matrix_a, 16, 16, 8, wmma::precision::tf32, wmma::row_major> a;
                wmma::fragment<wmma::matrix_b, 16, 16, 8, wmma::precision::tf32, wmma::row_major> bfr[2];
                wmma::load_matrix_sync(a, sm + SM_OFF + (wr * 16) * 20 + kk, 20);
#pragma unroll
                for (int e = 0; e < a.num_elements; e++) a.x[e] = wmma::__float_to_tf32(a.x[e]);
#pragma unroll
                for (int j = 0; j < 2; j++) {
                    wmma::load_matrix_sync(bfr[j], sm + SX_OFF + (s0 + kk) * 136 + h * 64 + wc * 32 + j * 16, 136);
#pragma unroll
                    for (int e = 0; e < bfr[j].num_elements; e++) bfr[j].x[e] = wmma::__float_to_tf32(bfr[j].x[e]);
                }
                wmma::mma_sync(accY[0], a, bfr[0], accY[0]);
                wmma::mma_sync(accY[1], a, bfr[1], accY[1]);
            }
            __syncthreads();
        }
        // store Y[h] into dead B/C pool: head h at offset h*8704, stride 68
#pragma unroll
        for (int j = 0; j < 2; j++)
            wmma::store_matrix_sync(sm + h * 8704 + (wr * 16) * 68 + wc * 32 + j * 16,
                                    accY[j], 68, wmma::mem_row_major);
    }
    __syncthreads();

    // ---- Phase 5: gate + RMSnorm, write to concat y buffer (orig order) ----
    {
        float Dv0 = Dp[pi * NHEADS + 0];
        float Dv1 = Dp[pi * NHEADS + 1];
        float nw0 = nw[(size_t)pi * DINNER + lane];
        float nw1 = nw[(size_t)pi * DINNER + lane + 32];
        float nw2 = nw[(size_t)pi * DINNER + lane + 64];
        float nw3 = nw[(size_t)pi * DINNER + lane + 96];

        for (int it = 0; it < 8; it++) {
            int t = it * 16 + warp;
            int orig = dir ? (127 - t) : t;
            const float* zr = zbase + (size_t)orig * ZLD;

            float y0 = sm[t * 68 + lane];
            float y1 = sm[t * 68 + lane + 32];
            float y2 = sm[8704 + t * 68 + lane];
            float y3 = sm[8704 + t * 68 + lane + 32];
            float x0 = sm[SX_OFF + t * 136 + lane];
            float x1 = sm[SX_OFF + t * 136 + lane + 32];
            float x2 = sm[SX_OFF + t * 136 + lane + 64];
            float x3 = sm[SX_OFF + t * 136 + lane + 96];
            float z0 = zr[lane], z1 = zr[lane + 32], z2 = zr[lane + 64], z3 = zr[lane + 96];

            float g0 = (y0 + Dv0 * x0) * (z0 / (1.f + __expf(-z0)));
            float g1 = (y1 + Dv0 * x1) * (z1 / (1.f + __expf(-z1)));
            float g2 = (y2 + Dv1 * x2) * (z2 / (1.f + __expf(-z2)));
            float g3 = (y3 + Dv1 * x3) * (z3 / (1.f + __expf(-z3)));

            float ss = g0 * g0 + g1 * g1 + g2 * g2 + g3 * g3;
#pragma unroll
            for (int off = 16; off; off >>= 1) ss += __shfl_xor_sync(0xffffffffu, ss, off);
            float rinv = rsqrtf(ss * (1.f / 128.f) + EPS);

            float* out = ybuf + ((size_t)(seq * LSEQ + orig)) * 256 + dir * 128;
            out[lane]      = g0 * rinv * nw0;
            out[lane + 32] = g1 * rinv * nw1;
            out[lane + 64] = g2 * rinv * nw2;
            out[lane + 96] = g3 * rinv * nw3;
        }
    }
}

// ---------------------------------------------------------------------------
// Residual add (+fusion bias) back into x (B,C,T,F) with stage permutation.
// ---------------------------------------------------------------------------
__global__ void resadd_kernel(float* __restrict__ x, const float* __restrict__ fused,
                              const float* __restrict__ fb, int stage)
{
    int i = blockIdx.x * blockDim.x + threadIdx.x;
    int f = i & 127, t = (i >> 7) & 127, c = (i >> 14) & 63, b = i >> 20;
    int token = (stage == 0) ? ((b * LSEQ + t) * LSEQ + f)
                             : ((b * LSEQ + f) * LSEQ + t);
    x[i] += fused[(size_t)token * DMODEL + c] + fb[c];
}

// ---------------------------------------------------------------------------
// Launch
// ---------------------------------------------------------------------------
extern "C" void kernel_launch(void* const* d_in, const int* in_sizes, int n_in,
                              void* d_out, int out_size)
{
    const float* x_in     = (const float*)d_in[0];
    const float* in_projW = (const float*)d_in[1];   // (4, 386, 64)
    const float* convW    = (const float*)d_in[2];   // (4, 256, 4)
    const float* convB    = (const float*)d_in[3];   // (4, 256)
    const float* dt_bias  = (const float*)d_in[4];   // (4, 2)
    const float* A_log    = (const float*)d_in[5];   // (4, 2)
    const float* D_param  = (const float*)d_in[6];   // (4, 2)
    const float* norm_w   = (const float*)d_in[7];   // (4, 128)
    const float* out_W    = (const float*)d_in[8];   // (4, 64, 128)
    const float* fusion_W = (const float*)d_in[9];   // (2, 64, 128)
    const float* fusion_b = (const float*)d_in[10];  // (2, 64)
    const float* ln_w     = (const float*)d_in[11];  // (2, 64)
    const float* ln_b     = (const float*)d_in[12];  // (2, 64)
    float* xo = (float*)d_out;                       // (4, 64, 128, 128) residual

    cudaFuncSetAttribute(ssd_kernel, cudaFuncAttributeMaxDynamicSharedMemorySize, SSD_SMEM);

    cudaMemcpyAsync(xo, x_in, (size_t)TOK * DMODEL * sizeof(float),
                    cudaMemcpyDeviceToDevice);

    float *p_u, *p_zx, *p_y, *p_fused, *p_wcomb;
    cudaGetSymbolAddress((void**)&p_u, g_u);
    cudaGetSymbolAddress((void**)&p_zx, g_zx);
    cudaGetSymbolAddress((void**)&p_y, g_y);
    cudaGetSymbolAddress((void**)&p_fused, g_fused);
    cudaGetSymbolAddress((void**)&p_wcomb, g_wcomb);

    wcomb_kernel<<<2, 256>>>(out_W, fusion_W, p_wcomb);

    for (int s = 0; s < 2; s++) {
        ln_kernel<<<TOK / 4, 128>>>(xo, ln_w + s * DMODEL, ln_b + s * DMODEL, p_u, s);

        // combined in_proj for both directions: u (65536x64) @ [Wp_2s;Wp_2s+1]^T
        {
            dim3 grid(13, TOK / 128);
            gemm_tf32<<<grid, 256>>>(p_u, in_projW + (size_t)(2 * s) * DPROJ * DMODEL,
                                     p_zx, TOK, 2 * DPROJ, DMODEL, ZLD);
        }

        // SSD: conv + dt + matrix scan + gate, both directions
        ssd_kernel<<<2 * NSEQ, 512, SSD_SMEM>>>(p_zx, convW, convB, dt_bias, A_log,
                                                D_param, norm_w, p_y, 2 * s);

        // combined out_proj + fusion GEMM: y (65536x256) @ Wcomb[s]^T (64x256)
        {
            dim3 grid(1, TOK / 128);
            gemm_tf32<<<grid, 256>>>(p_y, p_wcomb + (size_t)s * 64 * 256,
                                     p_fused, TOK, DMODEL, 256, DMODEL);
        }

        resadd_kernel<<<(TOK * DMODEL) / 256, 256>>>(xo, p_fused, fusion_b + s * DMODEL, s);
    }
}

// round 7
// speedup vs baseline: 2.2126x; 1.0090x over previous
#include <cuda_runtime.h>
#include <mma.h>
#include <math.h>

using namespace nvcuda;

// ---------------------------------------------------------------------------
// GridMambaBlock: B=4, C=64, T=128, F=128
// D_INNER=128, NHEADS=2, HEADDIM=64, D_STATE=64, CONV_DIM=256, D_IN_PROJ=386
// ---------------------------------------------------------------------------

#define TOK      65536
#define NSEQ     512
#define LSEQ     128
#define DMODEL   64
#define DINNER   128
#define NHEADS   2
#define CONVDIM  256
#define DPROJ    386
#define NPROJ2   772          // 2*DPROJ combined
#define ZLD      896          // padded row stride for combined zx (7 tiles x 128)
#define EPS      1e-5f

// SSD shared-memory pool offsets (floats)
#define SB_OFF   0            // B tile, stride 68, 128 rows   (later Y head0)
#define SC_OFF   8704         // C tile, stride 68             (later Y head1)
#define SG_OFF   17408        // G 128x128, stride 132
#define SX_OFF   34304        // X 128x128 (both heads), stride 136
#define SSD_SMEM ((34304 + 17408) * 4)   // 206848 bytes

// Scratch (device globals; allocation-free at runtime)
__device__ float g_xp[TOK * DMODEL];         // token-major permuted input
__device__ float g_zx[(size_t)TOK * ZLD];    // zxbcdt, both dirs in columns
__device__ float g_y[(size_t)TOK * 256];     // gated scan output, both dirs concat
__device__ float g_fused[TOK * DMODEL];      // fusion output
__device__ float g_wcomb[2][64 * 256];       // combined out_proj+fusion weights

// ---------------------------------------------------------------------------
// Tiled transpose: x (B,C,T,F) -> xperm[token][c], token-major.
// Block = (b, t): plane (c,f) 64x128. 512 blocks, 256 threads.
// ---------------------------------------------------------------------------
__global__ __launch_bounds__(256) void transpose_kernel(
    const float* __restrict__ x, float* __restrict__ xp, int stage)
{
    __shared__ float tile[64 * 129];
    int tid = threadIdx.x;
    int blk = blockIdx.x;
    int b = blk >> 7, t = blk & 127;
    const float* src = x + ((size_t)b * DMODEL * LSEQ + t) * LSEQ;  // + c*16384 + f
#pragma unroll
    for (int i = 0; i < 32; i++) {
        int id = i * 256 + tid;
        int c = id >> 7, f = id & 127;
        tile[c * 129 + f] = src[(size_t)c * 16384 + f];
    }
    __syncthreads();
#pragma unroll
    for (int i = 0; i < 32; i++) {
        int id = i * 256 + tid;
        int f = id >> 6, c = id & 63;
        size_t token = (stage == 0) ? ((size_t)(b * 128 + t) * 128 + f)
                                    : ((size_t)(b * 128 + f) * 128 + t);
        xp[token * DMODEL + c] = tile[c * 129 + f];
    }
}

// ---------------------------------------------------------------------------
// Fused LayerNorm + persistent in_proj GEMM.
// Block = seq (512 blocks, 256 threads). A slab 128x64 loaded once, LN'd in
// smem, then looped over 7 N-tiles (combined 772 rows of W). tf32 wmma.
// ---------------------------------------------------------------------------
__global__ __launch_bounds__(256) void inproj_kernel(
    const float* __restrict__ xp, const float* __restrict__ W,
    const float* __restrict__ lnw, const float* __restrict__ lnb,
    float* __restrict__ zxout)
{
    __shared__ float Asm[128 * 68];
    __shared__ float Wsm[128 * 68];
    const int tid = threadIdx.x;
    const int warp = tid >> 5;
    const int seq = blockIdx.x;

    // load A slab (contiguous 32KB) as float4
    const float4* src = (const float4*)(xp + (size_t)seq * 128 * DMODEL);
#pragma unroll
    for (int i = 0; i < 8; i++) {
        int id = i * 256 + tid;
        int row = id >> 4, c4 = id & 15;
        *(float4*)&Asm[row * 68 + c4 * 4] = src[id];
    }
    __syncthreads();

    // LayerNorm per row (2 threads per row, two-pass)
    {
        int row = tid >> 1, half = tid & 1;
        float* pr = Asm + row * 68 + half * 32;
        float s = 0.f;
#pragma unroll
        for (int j = 0; j < 32; j++) s += pr[j];
        s += __shfl_xor_sync(0xffffffffu, s, 1);
        float mean = s * (1.f / 64.f);
        float vs = 0.f;
#pragma unroll
        for (int j = 0; j < 32; j++) { float d = pr[j] - mean; vs += d * d; }
        vs += __shfl_xor_sync(0xffffffffu, vs, 1);
        float rstd = rsqrtf(vs * (1.f / 64.f) + EPS);
#pragma unroll
        for (int j = 0; j < 32; j++) {
            int c = half * 32 + j;
            pr[j] = (pr[j] - mean) * rstd * lnw[c] + lnb[c];
        }
    }
    __syncthreads();

    const int wr = (warp >> 1) * 32;   // row group of 32
    const int wc = (warp & 1) * 64;    // col group of 64

    for (int nt = 0; nt < 7; nt++) {
        int n0 = nt * 128;
        // load W tile 128x64 (row guard vs 772)
#pragma unroll
        for (int i = 0; i < 8; i++) {
            int id = i * 256 + tid;
            int row = id >> 4, c4 = id & 15;
            int gr = n0 + row;
            float4 v = make_float4(0.f, 0.f, 0.f, 0.f);
            if (gr < NPROJ2) v = *(const float4*)(W + (size_t)gr * 64 + c4 * 4);
            *(float4*)&Wsm[row * 68 + c4 * 4] = v;
        }
        __syncthreads();

        wmma::fragment<wmma::accumulator, 16, 16, 8, float> acc[2][4];
#pragma unroll
        for (int i = 0; i < 2; i++)
#pragma unroll
            for (int j = 0; j < 4; j++) wmma::fill_fragment(acc[i][j], 0.f);

#pragma unroll
        for (int k0 = 0; k0 < 64; k0 += 8) {
            wmma::fragment<wmma::matrix_a, 16, 16, 8, wmma::precision::tf32, wmma::row_major> a[2];
            wmma::fragment<wmma::matrix_b, 16, 16, 8, wmma::precision::tf32, wmma::col_major> bf[4];
#pragma unroll
            for (int i = 0; i < 2; i++) {
                wmma::load_matrix_sync(a[i], Asm + (wr + i * 16) * 68 + k0, 68);
#pragma unroll
                for (int e = 0; e < a[i].num_elements; e++) a[i].x[e] = wmma::__float_to_tf32(a[i].x[e]);
            }
#pragma unroll
            for (int j = 0; j < 4; j++) {
                wmma::load_matrix_sync(bf[j], Wsm + (wc + j * 16) * 68 + k0, 68);
#pragma unroll
                for (int e = 0; e < bf[j].num_elements; e++) bf[j].x[e] = wmma::__float_to_tf32(bf[j].x[e]);
            }
#pragma unroll
            for (int i = 0; i < 2; i++)
#pragma unroll
                for (int j = 0; j < 4; j++) wmma::mma_sync(acc[i][j], a[i], bf[j], acc[i][j]);
        }
        // store (cols 772..895 land in the in-row zx padding; never read)
#pragma unroll
        for (int i = 0; i < 2; i++)
#pragma unroll
            for (int j = 0; j < 4; j++)
                wmma::store_matrix_sync(zxout + (size_t)(seq * 128 + wr + i * 16) * ZLD + n0 + wc + j * 16,
                                        acc[i][j], ZLD, wmma::mem_row_major);
        __syncthreads();
    }
}

// ---------------------------------------------------------------------------
// tf32 wmma GEMM: C[M,N] = A[M,K] @ W[N,K]^T (out-proj+fusion path, N=64).
// ---------------------------------------------------------------------------
__global__ __launch_bounds__(256) void gemm_tf32(
    const float* __restrict__ A, const float* __restrict__ W,
    float* __restrict__ C, int M, int N, int K, int ldc)
{
    __shared__ float Asm[128 * 36];
    __shared__ float Wsm[64 * 36];
    const int tid = threadIdx.x;
    const int bm = blockIdx.y * 128, bn = blockIdx.x * 64;
    const int warp = tid >> 5;
    const int wr = (warp >> 1) * 32, wc = (warp & 1) * 32;

    wmma::fragment<wmma::accumulator, 16, 16, 8, float> acc[2][2];
#pragma unroll
    for (int i = 0; i < 2; i++)
#pragma unroll
        for (int j = 0; j < 2; j++) wmma::fill_fragment(acc[i][j], 0.f);

    for (int k0 = 0; k0 < K; k0 += 32) {
#pragma unroll
        for (int i = 0; i < 4; i++) {
            int id = tid + i * 256;
            int row = id >> 3, kq = id & 7;
            float4 v = make_float4(0.f, 0.f, 0.f, 0.f);
            int gm = bm + row;
            if (gm < M) v = *(const float4*)(A + (size_t)gm * K + k0 + kq * 4);
            *(float4*)&Asm[row * 36 + kq * 4] = v;
        }
#pragma unroll
        for (int i = 0; i < 2; i++) {
            int id = tid + i * 256;
            int row = id >> 3, kq = id & 7;
            float4 v = make_float4(0.f, 0.f, 0.f, 0.f);
            int gn = bn + row;
            if (gn < N) v = *(const float4*)(W + (size_t)gn * K + k0 + kq * 4);
            *(float4*)&Wsm[row * 36 + kq * 4] = v;
        }
        __syncthreads();

#pragma unroll
        for (int kk = 0; kk < 32; kk += 8) {
            wmma::fragment<wmma::matrix_a, 16, 16, 8, wmma::precision::tf32, wmma::row_major> a0, a1;
            wmma::fragment<wmma::matrix_b, 16, 16, 8, wmma::precision::tf32, wmma::col_major> b0, b1;
            wmma::load_matrix_sync(a0, Asm + (wr)      * 36 + kk, 36);
            wmma::load_matrix_sync(a1, Asm + (wr + 16) * 36 + kk, 36);
            wmma::load_matrix_sync(b0, Wsm + (wc)      * 36 + kk, 36);
            wmma::load_matrix_sync(b1, Wsm + (wc + 16) * 36 + kk, 36);
#pragma unroll
            for (int e = 0; e < a0.num_elements; e++) {
                a0.x[e] = wmma::__float_to_tf32(a0.x[e]);
                a1.x[e] = wmma::__float_to_tf32(a1.x[e]);
            }
#pragma unroll
            for (int e = 0; e < b0.num_elements; e++) {
                b0.x[e] = wmma::__float_to_tf32(b0.x[e]);
                b1.x[e] = wmma::__float_to_tf32(b1.x[e]);
            }
            wmma::mma_sync(acc[0][0], a0, b0, acc[0][0]);
            wmma::mma_sync(acc[0][1], a0, b1, acc[0][1]);
            wmma::mma_sync(acc[1][0], a1, b0, acc[1][0]);
            wmma::mma_sync(acc[1][1], a1, b1, acc[1][1]);
        }
        __syncthreads();
    }

#pragma unroll
    for (int i = 0; i < 2; i++)
#pragma unroll
        for (int j = 0; j < 2; j++)
            wmma::store_matrix_sync(C + (size_t)(bm + wr + i * 16) * ldc + bn + wc + j * 16,
                                    acc[i][j], ldc, wmma::mem_row_major);
}

// ---------------------------------------------------------------------------
// Precompute combined weights: W'[s][n][d*128+c] = sum_j Wf[s][n][d*64+j]*Wo[2s+d][j][c]
// ---------------------------------------------------------------------------
__global__ void wcomb_kernel(const float* __restrict__ outW,
                             const float* __restrict__ fusW,
                             float* __restrict__ wc)
{
    int s = blockIdx.x;
    for (int idx = threadIdx.x; idx < 64 * 256; idx += blockDim.x) {
        int n = idx >> 8, k = idx & 255;
        int d = k >> 7, c = k & 127;
        const float* wf = fusW + (size_t)(s * 64 + n) * 128 + d * 64;
        const float* wo = outW + (size_t)((s * 2 + d) * 64) * 128 + c;
        float acc = 0.f;
#pragma unroll
        for (int j = 0; j < 64; j++) acc += wf[j] * wo[(size_t)j * 128];
        wc[(size_t)s * 64 * 256 + idx] = acc;
    }
}

// ---------------------------------------------------------------------------
// SSD mega-kernel. Phase 4 = barrier-free raw mma.m16n8k8 with masked decay
// applied in registers (triangular skip saves real time now).
// ---------------------------------------------------------------------------
__global__ __launch_bounds__(512) void ssd_kernel(
    const float* __restrict__ zx, const float* __restrict__ convW,
    const float* __restrict__ convB, const float* __restrict__ dtb,
    const float* __restrict__ Al, const float* __restrict__ Dp,
    const float* __restrict__ nw, float* __restrict__ ybuf, int pi0)
{
    extern __shared__ float sm[];
    __shared__ float Ssm[2][128];
    __shared__ float dtsm[2][128];

    const int blk = blockIdx.x;
    const int dir = blk & 1;
    const int seq = blk >> 1;
    const int pi  = pi0 + dir;
    const int tid = threadIdx.x;
    const int warp = tid >> 5, lane = tid & 31;

    const float* zbase = zx + (size_t)seq * LSEQ * ZLD + dir * DPROJ;

    // ---- Phase 1: streaming causal conv (k=4) + SiLU into smem tiles ----
    {
        int c = tid & 255;
        int half = tid >> 8;
        int l0 = half * 64;
        const float4 w4 = *(const float4*)(convW + ((size_t)pi * CONVDIM + c) * 4);
        const float b = convB[pi * CONVDIM + c];
        const float* src = zbase + 128 + c;

        float h0 = 0.f, h1 = 0.f, h2 = 0.f;
        if (half) {
            int o1 = dir ? (127 - 61) : 61;
            int o2 = dir ? (127 - 62) : 62;
            int o3 = dir ? (127 - 63) : 63;
            h0 = src[(size_t)o1 * ZLD];
            h1 = src[(size_t)o2 * ZLD];
            h2 = src[(size_t)o3 * ZLD];
        }
        float* dst;
        int dstride;
        if (c < 128)      { dst = sm + SX_OFF + c;         dstride = 136; }
        else if (c < 192) { dst = sm + SB_OFF + (c - 128); dstride = 68; }
        else              { dst = sm + SC_OFF + (c - 192); dstride = 68; }

        for (int l = l0; l < l0 + 64; l++) {
            int orig = dir ? (127 - l) : l;
            float xin = src[(size_t)orig * ZLD];
            float v = w4.x * h0 + w4.y * h1 + w4.z * h2 + w4.w * xin + b;
            v = v / (1.f + __expf(-v));
            dst[l * dstride] = v;
            h0 = h1; h1 = h2; h2 = xin;
        }
    }

    // ---- Phase 2: dt softplus + cumsum S (warps 0,1 = heads 0,1) ----
    if (warp < 2) {
        int h = warp;
        float aexp = __expf(Al[pi * NHEADS + h]);
        float dtbh = dtb[pi * NHEADS + h];
        float dtv[4], csum[4];
        float run = 0.f;
#pragma unroll
        for (int k = 0; k < 4; k++) {
            int l = lane * 4 + k;
            int orig = dir ? (127 - l) : l;
            float raw = zbase[(size_t)orig * ZLD + 384 + h] + dtbh;
            float dt = (raw > 20.f) ? raw : log1pf(__expf(raw));
            run += aexp * dt;
            dtv[k] = dt; csum[k] = run;
        }
        float tot = run, scan = run;
#pragma unroll
        for (int off = 1; off < 32; off <<= 1) {
            float v = __shfl_up_sync(0xffffffffu, scan, off);
            if (lane >= off) scan += v;
        }
        float prefix = scan - tot;
#pragma unroll
        for (int k = 0; k < 4; k++) {
            int l = lane * 4 + k;
            Ssm[h][l] = prefix + csum[k];
            dtsm[h][l] = dtv[k];
        }
    }
    __syncthreads();

    // ---- Phase 3: G = C @ B^T (lower-triangular tiles only) ----
    {
        const int wt = warp >> 2, ws = warp & 3;
        if (ws <= wt) {
            wmma::fragment<wmma::accumulator, 16, 16, 8, float> accG[2][2];
#pragma unroll
            for (int i = 0; i < 2; i++)
#pragma unroll
                for (int j = 0; j < 2; j++) wmma::fill_fragment(accG[i][j], 0.f);

#pragma unroll
            for (int k0 = 0; k0 < 64; k0 += 8) {
                wmma::fragment<wmma::matrix_a, 16, 16, 8, wmma::precision::tf32, wmma::row_major> a[2];
                wmma::fragment<wmma::matrix_b, 16, 16, 8, wmma::precision::tf32, wmma::col_major> bfr[2];
#pragma unroll
                for (int i = 0; i < 2; i++) {
                    wmma::load_matrix_sync(a[i], sm + SC_OFF + (wt * 32 + i * 16) * 68 + k0, 68);
#pragma unroll
                    for (int e = 0; e < a[i].num_elements; e++) a[i].x[e] = wmma::__float_to_tf32(a[i].x[e]);
                }
#pragma unroll
                for (int j = 0; j < 2; j++) {
                    wmma::load_matrix_sync(bfr[j], sm + SB_OFF + (ws * 32 + j * 16) * 68 + k0, 68);
#pragma unroll
                    for (int e = 0; e < bfr[j].num_elements; e++) bfr[j].x[e] = wmma::__float_to_tf32(bfr[j].x[e]);
                }
#pragma unroll
                for (int i = 0; i < 2; i++)
#pragma unroll
                    for (int j = 0; j < 2; j++) wmma::mma_sync(accG[i][j], a[i], bfr[j], accG[i][j]);
            }
#pragma unroll
            for (int i = 0; i < 2; i++)
#pragma unroll
                for (int j = 0; j < 2; j++)
                    wmma::store_matrix_sync(sm + SG_OFF + (wt * 32 + i * 16) * 132 + ws * 32 + j * 16,
                                            accG[i][j], 132, wmma::mem_row_major);
        }
    }
    __syncthreads();   // G visible; B/C pool becomes Y

    // ---- Phase 4: barrier-free masked-decay Y = M @ X via raw mma ----
    {
        const int h  = warp >> 3;
        const int tt = warp & 7;
        const int tbase = tt * 16;
        const int gID = lane >> 2, tig = lane & 3;
        const int tA0 = tbase + gID, tA1 = tA0 + 8;
        const float St0 = Ssm[h][tA0], St1 = Ssm[h][tA1];

        float acc[8][4];
#pragma unroll
        for (int j = 0; j < 8; j++)
#pragma unroll
            for (int k = 0; k < 4; k++) acc[j][k] = 0.f;

        const int nchunks = 2 * tt + 2;
        for (int ch = 0; ch < nchunks; ch++) {
            int s0 = ch * 8;
            int sA0 = s0 + tig, sA1 = sA0 + 4;
            float Ss0 = Ssm[h][sA0], dt0 = dtsm[h][sA0];
            float Ss1 = Ssm[h][sA1], dt1 = dtsm[h][sA1];
            float a0 = (sA0 <= tA0) ? sm[SG_OFF + tA0 * 132 + sA0] * __expf(Ss0 - St0) * dt0 : 0.f;
            float a1 = (sA0 <= tA1) ? sm[SG_OFF + tA1 * 132 + sA0] * __expf(Ss0 - St1) * dt0 : 0.f;
            float a2 = (sA1 <= tA0) ? sm[SG_OFF + tA0 * 132 + sA1] * __expf(Ss1 - St0) * dt1 : 0.f;
            float a3 = (sA1 <= tA1) ? sm[SG_OFF + tA1 * 132 + sA1] * __expf(Ss1 - St1) * dt1 : 0.f;
            unsigned ua0, ua1, ua2, ua3;
            asm("cvt.rna.tf32.f32 %0, %1;" : "=r"(ua0) : "f"(a0));
            asm("cvt.rna.tf32.f32 %0, %1;" : "=r"(ua1) : "f"(a1));
            asm("cvt.rna.tf32.f32 %0, %1;" : "=r"(ua2) : "f"(a2));
            asm("cvt.rna.tf32.f32 %0, %1;" : "=r"(ua3) : "f"(a3));

            const float* Xb0 = sm + SX_OFF + (size_t)(s0 + tig) * 136 + h * 64 + gID;
            const float* Xb1 = Xb0 + 4 * 136;
#pragma unroll
            for (int j = 0; j < 8; j++) {
                float b0f = Xb0[j * 8], b1f = Xb1[j * 8];
                unsigned ub0, ub1;
                asm("cvt.rna.tf32.f32 %0, %1;" : "=r"(ub0) : "f"(b0f));
                asm("cvt.rna.tf32.f32 %0, %1;" : "=r"(ub1) : "f"(b1f));
                asm volatile(
                    "mma.sync.aligned.m16n8k8.row.col.f32.tf32.tf32.f32 "
                    "{%0,%1,%2,%3}, {%4,%5,%6,%7}, {%8,%9}, {%0,%1,%2,%3};\n"
                    : "+f"(acc[j][0]), "+f"(acc[j][1]), "+f"(acc[j][2]), "+f"(acc[j][3])
                    : "r"(ua0), "r"(ua1), "r"(ua2), "r"(ua3), "r"(ub0), "r"(ub1));
            }
        }
        // store Y fragments (d0: (gID, 2tig), d1: +1 col, d2/d3: row+8)
        float* yp = sm + h * 8704;
#pragma unroll
        for (int j = 0; j < 8; j++) {
            int col = j * 8 + 2 * tig;
            yp[tA0 * 68 + col]     = acc[j][0];
            yp[tA0 * 68 + col + 1] = acc[j][1];
            yp[tA1 * 68 + col]     = acc[j][2];
            yp[tA1 * 68 + col + 1] = acc[j][3];
        }
    }
    __syncthreads();

    // ---- Phase 5: gate + RMSnorm, write to concat y buffer (orig order) ----
    {
        float Dv0 = Dp[pi * NHEADS + 0];
        float Dv1 = Dp[pi * NHEADS + 1];
        float nw0 = nw[(size_t)pi * DINNER + lane];
        float nw1 = nw[(size_t)pi * DINNER + lane + 32];
        float nw2 = nw[(size_t)pi * DINNER + lane + 64];
        float nw3 = nw[(size_t)pi * DINNER + lane + 96];

        for (int it = 0; it < 8; it++) {
            int t = it * 16 + warp;
            int orig = dir ? (127 - t) : t;
            const float* zr = zbase + (size_t)orig * ZLD;

            float y0 = sm[t * 68 + lane];
            float y1 = sm[t * 68 + lane + 32];
            float y2 = sm[8704 + t * 68 + lane];
            float y3 = sm[8704 + t * 68 + lane + 32];
            float x0 = sm[SX_OFF + t * 136 + lane];
            float x1 = sm[SX_OFF + t * 136 + lane + 32];
            float x2 = sm[SX_OFF + t * 136 + lane + 64];
            float x3 = sm[SX_OFF + t * 136 + lane + 96];
            float z0 = zr[lane], z1 = zr[lane + 32], z2 = zr[lane + 64], z3 = zr[lane + 96];

            float g0 = (y0 + Dv0 * x0) * (z0 / (1.f + __expf(-z0)));
            float g1 = (y1 + Dv0 * x1) * (z1 / (1.f + __expf(-z1)));
            float g2 = (y2 + Dv1 * x2) * (z2 / (1.f + __expf(-z2)));
            float g3 = (y3 + Dv1 * x3) * (z3 / (1.f + __expf(-z3)));

            float ss = g0 * g0 + g1 * g1 + g2 * g2 + g3 * g3;
#pragma unroll
            for (int off = 16; off; off >>= 1) ss += __shfl_xor_sync(0xffffffffu, ss, off);
            float rinv = rsqrtf(ss * (1.f / 128.f) + EPS);

            float* out = ybuf + ((size_t)(seq * LSEQ + orig)) * 256 + dir * 128;
            out[lane]      = g0 * rinv * nw0;
            out[lane + 32] = g1 * rinv * nw1;
            out[lane + 64] = g2 * rinv * nw2;
            out[lane + 96] = g3 * rinv * nw3;
        }
    }
}

// ---------------------------------------------------------------------------
// Residual add (+fusion bias) back into x (B,C,T,F) with stage permutation.
// ---------------------------------------------------------------------------
__global__ void resadd_kernel(float* __restrict__ x, const float* __restrict__ fused,
                              const float* __restrict__ fb, int stage)
{
    int i = blockIdx.x * blockDim.x + threadIdx.x;
    int f = i & 127, t = (i >> 7) & 127, c = (i >> 14) & 63, b = i >> 20;
    int token = (stage == 0) ? ((b * LSEQ + t) * LSEQ + f)
                             : ((b * LSEQ + f) * LSEQ + t);
    x[i] += fused[(size_t)token * DMODEL + c] + fb[c];
}

// ---------------------------------------------------------------------------
// Launch
// ---------------------------------------------------------------------------
extern "C" void kernel_launch(void* const* d_in, const int* in_sizes, int n_in,
                              void* d_out, int out_size)
{
    const float* x_in     = (const float*)d_in[0];
    const float* in_projW = (const float*)d_in[1];   // (4, 386, 64)
    const float* convW    = (const float*)d_in[2];   // (4, 256, 4)
    const float* convB    = (const float*)d_in[3];   // (4, 256)
    const float* dt_bias  = (const float*)d_in[4];   // (4, 2)
    const float* A_log    = (const float*)d_in[5];   // (4, 2)
    const float* D_param  = (const float*)d_in[6];   // (4, 2)
    const float* norm_w   = (const float*)d_in[7];   // (4, 128)
    const float* out_W    = (const float*)d_in[8];   // (4, 64, 128)
    const float* fusion_W = (const float*)d_in[9];   // (2, 64, 128)
    const float* fusion_b = (const float*)d_in[10];  // (2, 64)
    const float* ln_w     = (const float*)d_in[11];  // (2, 64)
    const float* ln_b     = (const float*)d_in[12];  // (2, 64)
    float* xo = (float*)d_out;                       // (4, 64, 128, 128) residual

    cudaFuncSetAttribute(ssd_kernel, cudaFuncAttributeMaxDynamicSharedMemorySize, SSD_SMEM);

    cudaMemcpyAsync(xo, x_in, (size_t)TOK * DMODEL * sizeof(float),
                    cudaMemcpyDeviceToDevice);

    float *p_xp, *p_zx, *p_y, *p_fused, *p_wcomb;
    cudaGetSymbolAddress((void**)&p_xp, g_xp);
    cudaGetSymbolAddress((void**)&p_zx, g_zx);
    cudaGetSymbolAddress((void**)&p_y, g_y);
    cudaGetSymbolAddress((void**)&p_fused, g_fused);
    cudaGetSymbolAddress((void**)&p_wcomb, g_wcomb);

    wcomb_kernel<<<2, 256>>>(out_W, fusion_W, p_wcomb);

    for (int s = 0; s < 2; s++) {
        // permute residual to token-major
        transpose_kernel<<<NSEQ, 256>>>(xo, p_xp, s);

        // fused LN + combined in_proj (both directions)
        inproj_kernel<<<NSEQ, 256>>>(p_xp, in_projW + (size_t)(2 * s) * DPROJ * DMODEL,
                                     ln_w + s * DMODEL, ln_b + s * DMODEL, p_zx);

        // SSD: conv + dt + matrix scan + gate, both directions
        ssd_kernel<<<2 * NSEQ, 512, SSD_SMEM>>>(p_zx, convW, convB, dt_bias, A_log,
                                                D_param, norm_w, p_y, 2 * s);

        // combined out_proj + fusion GEMM: y (65536x256) @ Wcomb[s]^T (64x256)
        {
            dim3 grid(1, TOK / 128);
            gemm_tf32<<<grid, 256>>>(p_y, p_wcomb + (size_t)s * 64 * 256,
                                     p_fused, TOK, DMODEL, 256, DMODEL);
        }

        resadd_kernel<<<(TOK * DMODEL) / 256, 256>>>(xo, p_fused, fusion_b + s * DMODEL, s);
    }
}

// round 10
// speedup vs baseline: 2.5370x; 1.1466x over previous
#include <cuda_runtime.h>
#include <cuda_bf16.h>
#include <mma.h>
#include <math.h>
#include <stdint.h>

using namespace nvcuda;

// ---------------------------------------------------------------------------
// GridMambaBlock: B=4, C=64, T=128, F=128
// D_INNER=128, NHEADS=2, HEADDIM=64, D_STATE=64, CONV_DIM=256, D_IN_PROJ=386
// ---------------------------------------------------------------------------

#define TOK      65536
#define NSEQ     512
#define LSEQ     128
#define DMODEL   64
#define DINNER   128
#define NHEADS   2
#define CONVDIM  256
#define DPROJ    386
#define NPROJ2   772          // 2*DPROJ combined
#define ZLD      896          // padded row stride for combined zx (bf16)
#define EPS      1e-5f

// SSD shared-memory pool offsets (bf16 elements)
#define BS_OFF   0            // B tile [s][state], pitch 72
#define CS_OFF   9216         // C tile [t][state], pitch 72
#define XT_OFF   18432        // X transposed [p][s], pitch 136
#define G_OFF    35840        // G [t][s] bf16, pitch 136 (later Y [t][h*64+p])
#define SSD_SMEM (53248 * 2)  // 106496 bytes

// Scratch (device globals; allocation-free at runtime)
__device__ float g_xp[TOK * DMODEL];                 // token-major permuted input
__device__ __nv_bfloat16 g_zx[(size_t)TOK * ZLD];    // zxbcdt bf16, both dirs
__device__ float g_y[(size_t)TOK * 256];             // gated scan output (concat)
__device__ float g_fused[TOK * DMODEL];              // fusion output
__device__ float g_wcomb[2][64 * 256];               // combined out_proj+fusion W

// ---------------------------------------------------------------------------
// helpers
// ---------------------------------------------------------------------------
__device__ __forceinline__ uint32_t packbf2(float a, float b) {
    __nv_bfloat162 t = __floats2bfloat162_rn(a, b);
    return *reinterpret_cast<uint32_t*>(&t);
}
__device__ __forceinline__ float2 unpackbf2(uint32_t u) {
    __nv_bfloat162 t = *reinterpret_cast<__nv_bfloat162*>(&u);
    return __bfloat1622float2(t);
}
__device__ __forceinline__ uint32_t ld32(const __nv_bfloat16* p) {
    return *reinterpret_cast<const uint32_t*>(p);
}
__device__ __forceinline__ void st32(__nv_bfloat16* p, uint32_t v) {
    *reinterpret_cast<uint32_t*>(p) = v;
}
__device__ __forceinline__ void mma_bf16(float* c, uint32_t a0, uint32_t a1,
                                         uint32_t a2, uint32_t a3,
                                         uint32_t b0, uint32_t b1) {
    asm volatile(
        "mma.sync.aligned.m16n8k16.row.col.f32.bf16.bf16.f32 "
        "{%0,%1,%2,%3}, {%4,%5,%6,%7}, {%8,%9}, {%0,%1,%2,%3};\n"
        : "+f"(c[0]), "+f"(c[1]), "+f"(c[2]), "+f"(c[3])
        : "r"(a0), "r"(a1), "r"(a2), "r"(a3), "r"(b0), "r"(b1));
}

// ---------------------------------------------------------------------------
// Tiled transpose: x (B,C,T,F) -> xperm[token][c], token-major.
// ---------------------------------------------------------------------------
__global__ __launch_bounds__(256) void transpose_kernel(
    const float* __restrict__ x, float* __restrict__ xp, int stage)
{
    __shared__ float tile[64 * 129];
    int tid = threadIdx.x;
    int blk = blockIdx.x;
    int b = blk >> 7, t = blk & 127;
    const float* src = x + ((size_t)b * DMODEL * LSEQ + t) * LSEQ;
#pragma unroll
    for (int i = 0; i < 32; i++) {
        int id = i * 256 + tid;
        int c = id >> 7, f = id & 127;
        tile[c * 129 + f] = src[(size_t)c * 16384 + f];
    }
    __syncthreads();
#pragma unroll
    for (int i = 0; i < 32; i++) {
        int id = i * 256 + tid;
        int f = id >> 6, c = id & 63;
        size_t token = (stage == 0) ? ((size_t)(b * 128 + t) * 128 + f)
                                    : ((size_t)(b * 128 + f) * 128 + t);
        xp[token * DMODEL + c] = tile[c * 129 + f];
    }
}

// ---------------------------------------------------------------------------
// Fused LayerNorm + persistent in_proj GEMM -> bf16 zx.
// Block = seq (512 blocks, 256 threads). Fragments staged through Wsm, then
// converted to bf16 and written coalesced.
// ---------------------------------------------------------------------------
__global__ __launch_bounds__(256) void inproj_kernel(
    const float* __restrict__ xp, const float* __restrict__ W,
    const float* __restrict__ lnw, const float* __restrict__ lnb,
    __nv_bfloat16* __restrict__ zxout)
{
    __shared__ float Asm[128 * 68];
    __shared__ float Wsm[128 * 68];
    const int tid = threadIdx.x;
    const int warp = tid >> 5;
    const int seq = blockIdx.x;

    const float4* src = (const float4*)(xp + (size_t)seq * 128 * DMODEL);
#pragma unroll
    for (int i = 0; i < 8; i++) {
        int id = i * 256 + tid;
        int row = id >> 4, c4 = id & 15;
        *(float4*)&Asm[row * 68 + c4 * 4] = src[id];
    }
    __syncthreads();

    // LayerNorm per row (2 threads per row)
    {
        int row = tid >> 1, half = tid & 1;
        float* pr = Asm + row * 68 + half * 32;
        float s = 0.f;
#pragma unroll
        for (int j = 0; j < 32; j++) s += pr[j];
        s += __shfl_xor_sync(0xffffffffu, s, 1);
        float mean = s * (1.f / 64.f);
        float vs = 0.f;
#pragma unroll
        for (int j = 0; j < 32; j++) { float d = pr[j] - mean; vs += d * d; }
        vs += __shfl_xor_sync(0xffffffffu, vs, 1);
        float rstd = rsqrtf(vs * (1.f / 64.f) + EPS);
#pragma unroll
        for (int j = 0; j < 32; j++) {
            int c = half * 32 + j;
            pr[j] = (pr[j] - mean) * rstd * lnw[c] + lnb[c];
        }
    }
    __syncthreads();

    const int wr = (warp >> 1) * 32;
    const int wcg = warp & 1;          // col group (0: cols 0-63, 1: 64-127)
    const int stg_row = tid >> 1, stg_cb = (tid & 1) * 32;

    for (int nt = 0; nt < 7; nt++) {
        int n0 = nt * 128;
#pragma unroll
        for (int i = 0; i < 8; i++) {
            int id = i * 256 + tid;
            int row = id >> 4, c4 = id & 15;
            int gr = n0 + row;
            float4 v = make_float4(0.f, 0.f, 0.f, 0.f);
            if (gr < NPROJ2) v = *(const float4*)(W + (size_t)gr * 64 + c4 * 4);
            *(float4*)&Wsm[row * 68 + c4 * 4] = v;
        }
        __syncthreads();

        wmma::fragment<wmma::accumulator, 16, 16, 8, float> acc[2][4];
#pragma unroll
        for (int i = 0; i < 2; i++)
#pragma unroll
            for (int j = 0; j < 4; j++) wmma::fill_fragment(acc[i][j], 0.f);

#pragma unroll
        for (int k0 = 0; k0 < 64; k0 += 8) {
            wmma::fragment<wmma::matrix_a, 16, 16, 8, wmma::precision::tf32, wmma::row_major> a[2];
            wmma::fragment<wmma::matrix_b, 16, 16, 8, wmma::precision::tf32, wmma::col_major> bf[4];
#pragma unroll
            for (int i = 0; i < 2; i++) {
                wmma::load_matrix_sync(a[i], Asm + (wr + i * 16) * 68 + k0, 68);
#pragma unroll
                for (int e = 0; e < a[i].num_elements; e++) a[i].x[e] = wmma::__float_to_tf32(a[i].x[e]);
            }
#pragma unroll
            for (int j = 0; j < 4; j++) {
                wmma::load_matrix_sync(bf[j], Wsm + (wcg * 64 + j * 16) * 68 + k0, 68);
#pragma unroll
                for (int e = 0; e < bf[j].num_elements; e++) bf[j].x[e] = wmma::__float_to_tf32(bf[j].x[e]);
            }
#pragma unroll
            for (int i = 0; i < 2; i++)
#pragma unroll
                for (int j = 0; j < 4; j++) wmma::mma_sync(acc[i][j], a[i], bf[j], acc[i][j]);
        }
        __syncthreads();   // done reading Wsm; reuse as stage

        // two col-halves: stage fp32 -> convert bf16 -> global
#pragma unroll
        for (int hc = 0; hc < 2; hc++) {
            if (wcg == hc) {
#pragma unroll
                for (int i = 0; i < 2; i++)
#pragma unroll
                    for (int j = 0; j < 4; j++)
                        wmma::store_matrix_sync(Wsm + (wr + i * 16) * 68 + j * 16,
                                                acc[i][j], 68, wmma::mem_row_major);
            }
            __syncthreads();
            {
                __nv_bfloat16* dst = zxout + (size_t)(seq * 128 + stg_row) * ZLD
                                     + n0 + hc * 64 + stg_cb;
                const float* srow = Wsm + stg_row * 68 + stg_cb;
#pragma unroll
                for (int k = 0; k < 16; k++)
                    st32(dst + 2 * k, packbf2(srow[2 * k], srow[2 * k + 1]));
            }
            __syncthreads();
        }
    }
}

// ---------------------------------------------------------------------------
// tf32 wmma GEMM: C[M,N] = A[M,K] @ W[N,K]^T (out-proj+fusion path).
// ---------------------------------------------------------------------------
__global__ __launch_bounds__(256) void gemm_tf32(
    const float* __restrict__ A, const float* __restrict__ W,
    float* __restrict__ C, int M, int N, int K, int ldc)
{
    __shared__ float Asm[128 * 36];
    __shared__ float Wsm[64 * 36];
    const int tid = threadIdx.x;
    const int bm = blockIdx.y * 128, bn = blockIdx.x * 64;
    const int warp = tid >> 5;
    const int wr = (warp >> 1) * 32, wc = (warp & 1) * 32;

    wmma::fragment<wmma::accumulator, 16, 16, 8, float> acc[2][2];
#pragma unroll
    for (int i = 0; i < 2; i++)
#pragma unroll
        for (int j = 0; j < 2; j++) wmma::fill_fragment(acc[i][j], 0.f);

    for (int k0 = 0; k0 < K; k0 += 32) {
#pragma unroll
        for (int i = 0; i < 4; i++) {
            int id = tid + i * 256;
            int row = id >> 3, kq = id & 7;
            float4 v = make_float4(0.f, 0.f, 0.f, 0.f);
            int gm = bm + row;
            if (gm < M) v = *(const float4*)(A + (size_t)gm * K + k0 + kq * 4);
            *(float4*)&Asm[row * 36 + kq * 4] = v;
        }
#pragma unroll
        for (int i = 0; i < 2; i++) {
            int id = tid + i * 256;
            int row = id >> 3, kq = id & 7;
            float4 v = make_float4(0.f, 0.f, 0.f, 0.f);
            int gn = bn + row;
            if (gn < N) v = *(const float4*)(W + (size_t)gn * K + k0 + kq * 4);
            *(float4*)&Wsm[row * 36 + kq * 4] = v;
        }
        __syncthreads();

#pragma unroll
        for (int kk = 0; kk < 32; kk += 8) {
            wmma::fragment<wmma::matrix_a, 16, 16, 8, wmma::precision::tf32, wmma::row_major> a0, a1;
            wmma::fragment<wmma::matrix_b, 16, 16, 8, wmma::precision::tf32, wmma::col_major> b0, b1;
            wmma::load_matrix_sync(a0, Asm + (wr)      * 36 + kk, 36);
            wmma::load_matrix_sync(a1, Asm + (wr + 16) * 36 + kk, 36);
            wmma::load_matrix_sync(b0, Wsm + (wc)      * 36 + kk, 36);
            wmma::load_matrix_sync(b1, Wsm + (wc + 16) * 36 + kk, 36);
#pragma unroll
            for (int e = 0; e < a0.num_elements; e++) {
                a0.x[e] = wmma::__float_to_tf32(a0.x[e]);
                a1.x[e] = wmma::__float_to_tf32(a1.x[e]);
            }
#pragma unroll
            for (int e = 0; e < b0.num_elements; e++) {
                b0.x[e] = wmma::__float_to_tf32(b0.x[e]);
                b1.x[e] = wmma::__float_to_tf32(b1.x[e]);
            }
            wmma::mma_sync(acc[0][0], a0, b0, acc[0][0]);
            wmma::mma_sync(acc[0][1], a0, b1, acc[0][1]);
            wmma::mma_sync(acc[1][0], a1, b0, acc[1][0]);
            wmma::mma_sync(acc[1][1], a1, b1, acc[1][1]);
        }
        __syncthreads();
    }

#pragma unroll
    for (int i = 0; i < 2; i++)
#pragma unroll
        for (int j = 0; j < 2; j++)
            wmma::store_matrix_sync(C + (size_t)(bm + wr + i * 16) * ldc + bn + wc + j * 16,
                                    acc[i][j], ldc, wmma::mem_row_major);
}

// ---------------------------------------------------------------------------
// Precompute combined weights
// ---------------------------------------------------------------------------
__global__ void wcomb_kernel(const float* __restrict__ outW,
                             const float* __restrict__ fusW,
                             float* __restrict__ wc)
{
    int s = blockIdx.x;
    for (int idx = threadIdx.x; idx < 64 * 256; idx += blockDim.x) {
        int n = idx >> 8, k = idx & 255;
        int d = k >> 7, c = k & 127;
        const float* wf = fusW + (size_t)(s * 64 + n) * 128 + d * 64;
        const float* wo = outW + (size_t)((s * 2 + d) * 64) * 128 + c;
        float acc = 0.f;
#pragma unroll
        for (int j = 0; j < 64; j++) acc += wf[j] * wo[(size_t)j * 128];
        wc[(size_t)s * 64 * 256 + idx] = acc;
    }
}

// ---------------------------------------------------------------------------
// SSD mega-kernel, all-bf16 tiles, 104KB smem, 2 blocks/SM.
// ---------------------------------------------------------------------------
__global__ __launch_bounds__(512, 2) void ssd_kernel(
    const __nv_bfloat16* __restrict__ zx, const float* __restrict__ convW,
    const float* __restrict__ convB, const float* __restrict__ dtb,
    const float* __restrict__ Al, const float* __restrict__ Dp,
    const float* __restrict__ nw, float* __restrict__ ybuf, int pi0)
{
    extern __shared__ __nv_bfloat16 pool[];
    __shared__ float Ssm[2][128];
    __shared__ float dtsm[2][128];

    __nv_bfloat16* Bs = pool + BS_OFF;   // [s][state] pitch 72
    __nv_bfloat16* Cs = pool + CS_OFF;   // [t][state] pitch 72
    __nv_bfloat16* Xt = pool + XT_OFF;   // [p][s]     pitch 136
    __nv_bfloat16* G  = pool + G_OFF;    // [t][s]     pitch 136 (later Y)

    const int blk = blockIdx.x;
    const int dir = blk & 1;
    const int seq = blk >> 1;
    const int pi  = pi0 + dir;
    const int tid = threadIdx.x;
    const int warp = tid >> 5, lane = tid & 31;
    const int gID = lane >> 2, tig = lane & 3;

    const __nv_bfloat16* zbase = zx + (size_t)seq * LSEQ * ZLD + dir * DPROJ;

    // ---- Phase 1: streaming causal conv (k=4) + SiLU into bf16 tiles ----
    {
        int c = tid & 255;
        int half = tid >> 8;
        int l0 = half * 64;
        const float4 w4 = *(const float4*)(convW + ((size_t)pi * CONVDIM + c) * 4);
        const float b = convB[pi * CONVDIM + c];
        const __nv_bfloat16* src = zbase + 128 + c;

        float h0 = 0.f, h1 = 0.f, h2 = 0.f;
        if (half) {
            int o1 = dir ? (127 - 61) : 61;
            int o2 = dir ? (127 - 62) : 62;
            int o3 = dir ? (127 - 63) : 63;
            h0 = __bfloat162float(src[(size_t)o1 * ZLD]);
            h1 = __bfloat162float(src[(size_t)o2 * ZLD]);
            h2 = __bfloat162float(src[(size_t)o3 * ZLD]);
        }
        __nv_bfloat16* dst;
        int dstride;
        if (c < 128)      { dst = Xt + (size_t)c * 136;  dstride = 1;  }   // Xt[p][l]
        else if (c < 192) { dst = Bs + (c - 128);        dstride = 72; }   // Bs[l][k]
        else              { dst = Cs + (c - 192);        dstride = 72; }   // Cs[l][k]

        for (int l = l0; l < l0 + 64; l++) {
            int orig = dir ? (127 - l) : l;
            float xin = __bfloat162float(src[(size_t)orig * ZLD]);
            float v = w4.x * h0 + w4.y * h1 + w4.z * h2 + w4.w * xin + b;
            v = v / (1.f + __expf(-v));
            dst[l * dstride] = __float2bfloat16(v);
            h0 = h1; h1 = h2; h2 = xin;
        }
    }

    // ---- Phase 2: dt softplus + cumsum S (warps 0,1 = heads 0,1) ----
    if (warp < 2) {
        int h = warp;
        float aexp = __expf(Al[pi * NHEADS + h]);
        float dtbh = dtb[pi * NHEADS + h];
        float dtv[4], csum[4];
        float run = 0.f;
#pragma unroll
        for (int k = 0; k < 4; k++) {
            int l = lane * 4 + k;
            int orig = dir ? (127 - l) : l;
            float raw = __bfloat162float(zbase[(size_t)orig * ZLD + 384 + h]) + dtbh;
            float dt = (raw > 20.f) ? raw : log1pf(__expf(raw));
            run += aexp * dt;
            dtv[k] = dt; csum[k] = run;
        }
        float tot = run, scan = run;
#pragma unroll
        for (int off = 1; off < 32; off <<= 1) {
            float v = __shfl_up_sync(0xffffffffu, scan, off);
            if (lane >= off) scan += v;
        }
        float prefix = scan - tot;
#pragma unroll
        for (int k = 0; k < 4; k++) {
            int l = lane * 4 + k;
            Ssm[h][l] = prefix + csum[k];
            dtsm[h][l] = dtv[k];
        }
    }
    __syncthreads();

    // ---- Phase 3: G = C @ B^T, bf16 raw mma, 72 triangular tiles / 16 warps ----
    for (int k4 = warp; k4 < 72; k4 += 16) {
        int tt = 0;
        while ((tt + 1) * (tt + 2) <= k4) tt++;
        int st = k4 - tt * (tt + 1);
        int t0 = tt * 16, s0 = st * 8;
        float acc[4] = {0.f, 0.f, 0.f, 0.f};
#pragma unroll
        for (int k0 = 0; k0 < 64; k0 += 16) {
            uint32_t a0 = ld32(Cs + (t0 + gID) * 72 + k0 + 2 * tig);
            uint32_t a1 = ld32(Cs + (t0 + gID + 8) * 72 + k0 + 2 * tig);
            uint32_t a2 = ld32(Cs + (t0 + gID) * 72 + k0 + 2 * tig + 8);
            uint32_t a3 = ld32(Cs + (t0 + gID + 8) * 72 + k0 + 2 * tig + 8);
            uint32_t b0 = ld32(Bs + (s0 + gID) * 72 + k0 + 2 * tig);
            uint32_t b1 = ld32(Bs + (s0 + gID) * 72 + k0 + 2 * tig + 8);
            mma_bf16(acc, a0, a1, a2, a3, b0, b1);
        }
        st32(G + (t0 + gID) * 136 + s0 + 2 * tig, packbf2(acc[0], acc[1]));
        st32(G + (t0 + gID + 8) * 136 + s0 + 2 * tig, packbf2(acc[2], acc[3]));
    }
    __syncthreads();

    // ---- Phase 4: Y = (G.*decay.*dt, causal) @ X, bf16 raw mma ----
    {
        const int h = warp >> 3;
        const int tt = warp & 7;
        const int t0 = tt * 16;
        const int tA0 = t0 + gID, tA1 = tA0 + 8;
        const float St0 = Ssm[h][tA0], St1 = Ssm[h][tA1];

        float acc[8][4];
#pragma unroll
        for (int j = 0; j < 8; j++)
#pragma unroll
            for (int k = 0; k < 4; k++) acc[j][k] = 0.f;

        for (int ch = 0; ch <= tt; ch++) {
            int s0 = ch * 16;
            int sa = s0 + 2 * tig;
            int sb = sa + 8;
            float2 g00 = unpackbf2(ld32(G + tA0 * 136 + sa));
            float2 g10 = unpackbf2(ld32(G + tA1 * 136 + sa));
            float2 g01 = unpackbf2(ld32(G + tA0 * 136 + sb));
            float2 g11 = unpackbf2(ld32(G + tA1 * 136 + sb));
            float Sa0 = Ssm[h][sa], Sa1 = Ssm[h][sa + 1];
            float Sb0 = Ssm[h][sb], Sb1 = Ssm[h][sb + 1];
            float da0 = dtsm[h][sa], da1 = dtsm[h][sa + 1];
            float db0 = dtsm[h][sb], db1 = dtsm[h][sb + 1];
            bool diag = (ch == tt);

            float m00 = (!diag || sa     <= tA0) ? g00.x * __expf(Sa0 - St0) * da0 : 0.f;
            float m01 = (!diag || sa + 1 <= tA0) ? g00.y * __expf(Sa1 - St0) * da1 : 0.f;
            float m10 = (!diag || sa     <= tA1) ? g10.x * __expf(Sa0 - St1) * da0 : 0.f;
            float m11 = (!diag || sa + 1 <= tA1) ? g10.y * __expf(Sa1 - St1) * da1 : 0.f;
            float m20 = (!diag || sb     <= tA0) ? g01.x * __expf(Sb0 - St0) * db0 : 0.f;
            float m21 = (!diag || sb + 1 <= tA0) ? g01.y * __expf(Sb1 - St0) * db1 : 0.f;
            float m30 = (!diag || sb     <= tA1) ? g11.x * __expf(Sb0 - St1) * db0 : 0.f;
            float m31 = (!diag || sb + 1 <= tA1) ? g11.y * __expf(Sb1 - St1) * db1 : 0.f;

            uint32_t ua0 = packbf2(m00, m01);
            uint32_t ua1 = packbf2(m10, m11);
            uint32_t ua2 = packbf2(m20, m21);
            uint32_t ua3 = packbf2(m30, m31);

            const __nv_bfloat16* xb = Xt + (size_t)(h * 64 + gID) * 136;
#pragma unroll
            for (int j = 0; j < 8; j++) {
                uint32_t b0 = ld32(xb + (size_t)j * 8 * 136 + sa);
                uint32_t b1 = ld32(xb + (size_t)j * 8 * 136 + sb);
                mma_bf16(acc[j], ua0, ua1, ua2, ua3, b0, b1);
            }
        }
        __syncthreads();   // all warps done reading G before Y overwrites it

#pragma unroll
        for (int j = 0; j < 8; j++) {
            int col = h * 64 + j * 8 + 2 * tig;
            st32(G + tA0 * 136 + col, packbf2(acc[j][0], acc[j][1]));
            st32(G + tA1 * 136 + col, packbf2(acc[j][2], acc[j][3]));
        }
    }
    __syncthreads();

    // ---- Phase 5: gate + RMSnorm, write concat y buffer (orig order) ----
    {
        float Dv0 = Dp[pi * NHEADS + 0];
        float Dv1 = Dp[pi * NHEADS + 1];
        float nw0 = nw[(size_t)pi * DINNER + lane];
        float nw1 = nw[(size_t)pi * DINNER + lane + 32];
        float nw2 = nw[(size_t)pi * DINNER + lane + 64];
        float nw3 = nw[(size_t)pi * DINNER + lane + 96];

        for (int it = 0; it < 8; it++) {
            int t = it * 16 + warp;
            int orig = dir ? (127 - t) : t;
            const __nv_bfloat16* zr = zbase + (size_t)orig * ZLD;

            float y0 = __bfloat162float(G[t * 136 + lane]);
            float y1 = __bfloat162float(G[t * 136 + lane + 32]);
            float y2 = __bfloat162float(G[t * 136 + lane + 64]);
            float y3 = __bfloat162float(G[t * 136 + lane + 96]);
            float x0 = __bfloat162float(Xt[(size_t)lane * 136 + t]);
            float x1 = __bfloat162float(Xt[(size_t)(lane + 32) * 136 + t]);
            float x2 = __bfloat162float(Xt[(size_t)(lane + 64) * 136 + t]);
            float x3 = __bfloat162float(Xt[(size_t)(lane + 96) * 136 + t]);
            float z0 = __bfloat162float(zr[lane]);
            float z1 = __bfloat162float(zr[lane + 32]);
            float z2 = __bfloat162float(zr[lane + 64]);
            float z3 = __bfloat162float(zr[lane + 96]);

            float g0 = (y0 + Dv0 * x0) * (z0 / (1.f + __expf(-z0)));
            float g1 = (y1 + Dv0 * x1) * (z1 / (1.f + __expf(-z1)));
            float g2 = (y2 + Dv1 * x2) * (z2 / (1.f + __expf(-z2)));
            float g3 = (y3 + Dv1 * x3) * (z3 / (1.f + __expf(-z3)));

            float ss = g0 * g0 + g1 * g1 + g2 * g2 + g3 * g3;
#pragma unroll
            for (int off = 16; off; off >>= 1) ss += __shfl_xor_sync(0xffffffffu, ss, off);
            float rinv = rsqrtf(ss * (1.f / 128.f) + EPS);

            float* out = ybuf + ((size_t)(seq * LSEQ + orig)) * 256 + dir * 128;
            out[lane]      = g0 * rinv * nw0;
            out[lane + 32] = g1 * rinv * nw1;
            out[lane + 64] = g2 * rinv * nw2;
            out[lane + 96] = g3 * rinv * nw3;
        }
    }
}

// ---------------------------------------------------------------------------
// Residual add (+fusion bias) back into x (B,C,T,F) with stage permutation.
// ---------------------------------------------------------------------------
__global__ void resadd_kernel(float* __restrict__ x, const float* __restrict__ fused,
                              const float* __restrict__ fb, int stage)
{
    int i = blockIdx.x * blockDim.x + threadIdx.x;
    int f = i & 127, t = (i >> 7) & 127, c = (i >> 14) & 63, b = i >> 20;
    int token = (stage == 0) ? ((b * LSEQ + t) * LSEQ + f)
                             : ((b * LSEQ + f) * LSEQ + t);
    x[i] += fused[(size_t)token * DMODEL + c] + fb[c];
}

// ---------------------------------------------------------------------------
// Launch
// ---------------------------------------------------------------------------
extern "C" void kernel_launch(void* const* d_in, const int* in_sizes, int n_in,
                              void* d_out, int out_size)
{
    const float* x_in     = (const float*)d_in[0];
    const float* in_projW = (const float*)d_in[1];
    const float* convW    = (const float*)d_in[2];
    const float* convB    = (const float*)d_in[3];
    const float* dt_bias  = (const float*)d_in[4];
    const float* A_log    = (const float*)d_in[5];
    const float* D_param  = (const float*)d_in[6];
    const float* norm_w   = (const float*)d_in[7];
    const float* out_W    = (const float*)d_in[8];
    const float* fusion_W = (const float*)d_in[9];
    const float* fusion_b = (const float*)d_in[10];
    const float* ln_w     = (const float*)d_in[11];
    const float* ln_b     = (const float*)d_in[12];
    float* xo = (float*)d_out;

    cudaFuncSetAttribute(ssd_kernel, cudaFuncAttributeMaxDynamicSharedMemorySize, SSD_SMEM);

    cudaMemcpyAsync(xo, x_in, (size_t)TOK * DMODEL * sizeof(float),
                    cudaMemcpyDeviceToDevice);

    float *p_xp, *p_y, *p_fused, *p_wcomb;
    __nv_bfloat16* p_zx;
    cudaGetSymbolAddress((void**)&p_xp, g_xp);
    cudaGetSymbolAddress((void**)&p_zx, g_zx);
    cudaGetSymbolAddress((void**)&p_y, g_y);
    cudaGetSymbolAddress((void**)&p_fused, g_fused);
    cudaGetSymbolAddress((void**)&p_wcomb, g_wcomb);

    wcomb_kernel<<<2, 256>>>(out_W, fusion_W, p_wcomb);

    for (int s = 0; s < 2; s++) {
        transpose_kernel<<<NSEQ, 256>>>(xo, p_xp, s);

        inproj_kernel<<<NSEQ, 256>>>(p_xp, in_projW + (size_t)(2 * s) * DPROJ * DMODEL,
                                     ln_w + s * DMODEL, ln_b + s * DMODEL, p_zx);

        ssd_kernel<<<2 * NSEQ, 512, SSD_SMEM>>>(p_zx, convW, convB, dt_bias, A_log,
                                                D_param, norm_w, p_y, 2 * s);

        {
            dim3 grid(1, TOK / 128);
            gemm_tf32<<<grid, 256>>>(p_y, p_wcomb + (size_t)s * 64 * 256,
                                     p_fused, TOK, DMODEL, 256, DMODEL);
        }

        resadd_kernel<<<(TOK * DMODEL) / 256, 256>>>(xo, p_fused, fusion_b + s * DMODEL, s);
    }
}

// round 12
// speedup vs baseline: 4.3007x; 1.6952x over previous
#include <cuda_runtime.h>
#include <cuda_bf16.h>
#include <mma.h>
#include <math.h>
#include <stdint.h>

// ---------------------------------------------------------------------------
// GridMambaBlock: B=4, C=64, T=128, F=128
// ---------------------------------------------------------------------------

#define TOK      65536
#define NSEQ     512
#define LSEQ     128
#define DMODEL   64
#define DINNER   128
#define NHEADS   2
#define CONVDIM  256
#define DPROJ    386
#define NPROJ2   772
#define WROWS    896          // padded combined in_proj rows per stage
#define ZLD      896          // zx row stride (bf16)
#define EPS      1e-5f

// SSD smem pool offsets (bf16 elements)
#define BS_OFF   0
#define CS_OFF   9216
#define XT_OFF   18432
#define G_OFF    35840
#define SSD_SMEM (53248 * 2)

// inproj dynamic smem (bf16 units): Asm[128][72], Wsm[128][72], Stg[128][136]
#define IP_ASM   0
#define IP_WSM   9216
#define IP_STG   18432
#define IP_SMEM  ((18432 + 17408) * 2)      // 71680 B

// outgemm dynamic smem: Ysm[128][72] bf16, Wsm[64][72] bf16, Ct[64][132] fp32
#define OG_YSM   0
#define OG_WSM   9216
#define OG_CT_B  ((9216 + 4608) * 2)        // byte offset of Ct
#define OG_SMEM  (OG_CT_B + 64 * 132 * 4)   // 61440 B

// Scratch (device globals)
__device__ float g_xp[TOK * DMODEL];
__device__ __nv_bfloat16 g_zx[(size_t)TOK * ZLD];
__device__ __nv_bfloat16 g_y[(size_t)TOK * 256];
__device__ __nv_bfloat16 g_wbf[2][WROWS * DMODEL];     // in_proj W bf16, padded
__device__ __nv_bfloat16 g_wcomb[2][64 * 256];         // combined out W bf16

// ---------------------------------------------------------------------------
// helpers
// ---------------------------------------------------------------------------
__device__ __forceinline__ uint32_t packbf2(float a, float b) {
    __nv_bfloat162 t = __floats2bfloat162_rn(a, b);
    return *reinterpret_cast<uint32_t*>(&t);
}
__device__ __forceinline__ float2 unpackbf2(uint32_t u) {
    __nv_bfloat162 t = *reinterpret_cast<__nv_bfloat162*>(&u);
    return __bfloat1622float2(t);
}
__device__ __forceinline__ uint32_t ld32(const __nv_bfloat16* p) {
    return *reinterpret_cast<const uint32_t*>(p);
}
__device__ __forceinline__ void st32(__nv_bfloat16* p, uint32_t v) {
    *reinterpret_cast<uint32_t*>(p) = v;
}
__device__ __forceinline__ void mma_bf16(float* c, uint32_t a0, uint32_t a1,
                                         uint32_t a2, uint32_t a3,
                                         uint32_t b0, uint32_t b1) {
    asm volatile(
        "mma.sync.aligned.m16n8k16.row.col.f32.bf16.bf16.f32 "
        "{%0,%1,%2,%3}, {%4,%5,%6,%7}, {%8,%9}, {%0,%1,%2,%3};\n"
        : "+f"(c[0]), "+f"(c[1]), "+f"(c[2]), "+f"(c[3])
        : "r"(a0), "r"(a1), "r"(a2), "r"(a3), "r"(b0), "r"(b1));
}

// ---------------------------------------------------------------------------
// Weight prep: in_proj -> bf16 padded [2][896][64]
// ---------------------------------------------------------------------------
__global__ void wprep_kernel(const float* __restrict__ W, __nv_bfloat16* __restrict__ wb)
{
    int s = blockIdx.x;
    for (int idx = threadIdx.x; idx < WROWS * DMODEL; idx += blockDim.x) {
        int row = idx >> 6, c = idx & 63;
        float v = 0.f;
        if (row < NPROJ2) {
            int pi = 2 * s + (row >= DPROJ);
            int r = (row >= DPROJ) ? row - DPROJ : row;
            v = W[((size_t)pi * DPROJ + r) * DMODEL + c];
        }
        wb[(size_t)s * WROWS * DMODEL + idx] = __float2bfloat16(v);
    }
}

// ---------------------------------------------------------------------------
// Combined out_proj+fusion weights -> bf16
// ---------------------------------------------------------------------------
__global__ void wcomb_kernel(const float* __restrict__ outW,
                             const float* __restrict__ fusW,
                             __nv_bfloat16* __restrict__ wc)
{
    int s = blockIdx.x;
    for (int idx = threadIdx.x; idx < 64 * 256; idx += blockDim.x) {
        int n = idx >> 8, k = idx & 255;
        int d = k >> 7, c = k & 127;
        const float* wf = fusW + (size_t)(s * 64 + n) * 128 + d * 64;
        const float* wo = outW + (size_t)((s * 2 + d) * 64) * 128 + c;
        float acc = 0.f;
#pragma unroll
        for (int j = 0; j < 64; j++) acc += wf[j] * wo[(size_t)j * 128];
        wc[(size_t)s * 64 * 256 + idx] = __float2bfloat16(acc);
    }
}

// ---------------------------------------------------------------------------
// Tiled transpose: x (B,C,T,F) -> xperm[token][c]
// ---------------------------------------------------------------------------
__global__ __launch_bounds__(256) void transpose_kernel(
    const float* __restrict__ x, float* __restrict__ xp, int stage)
{
    __shared__ float tile[64 * 129];
    int tid = threadIdx.x;
    int blk = blockIdx.x;
    int b = blk >> 7, t = blk & 127;
    const float* src = x + ((size_t)b * DMODEL * LSEQ + t) * LSEQ;
#pragma unroll
    for (int i = 0; i < 32; i++) {
        int id = i * 256 + tid;
        int c = id >> 7, f = id & 127;
        tile[c * 129 + f] = src[(size_t)c * 16384 + f];
    }
    __syncthreads();
#pragma unroll
    for (int i = 0; i < 32; i++) {
        int id = i * 256 + tid;
        int f = id >> 6, c = id & 63;
        size_t token = (stage == 0) ? ((size_t)(b * 128 + t) * 128 + f)
                                    : ((size_t)(b * 128 + f) * 128 + t);
        xp[token * DMODEL + c] = tile[c * 129 + f];
    }
}

// ---------------------------------------------------------------------------
// Fused LayerNorm + in_proj (bf16 raw mma) -> bf16 zx. Block = seq, 256 thr.
// ---------------------------------------------------------------------------
__global__ __launch_bounds__(256) void inproj_kernel(
    const float* __restrict__ xp, const __nv_bfloat16* __restrict__ Wb,
    const float* __restrict__ lnw, const float* __restrict__ lnb,
    __nv_bfloat16* __restrict__ zxout)
{
    extern __shared__ __nv_bfloat16 ip[];
    __nv_bfloat16* Asm = ip + IP_ASM;   // [128][72]
    __nv_bfloat16* Wsm = ip + IP_WSM;   // [128][72]
    __nv_bfloat16* Stg = ip + IP_STG;   // [128][136]

    const int tid = threadIdx.x;
    const int warp = tid >> 5, lane = tid & 31;
    const int gID = lane >> 2, tig = lane & 3;
    const int seq = blockIdx.x;

    // ---- load + LayerNorm (2 threads per row, in registers) -> Asm bf16 ----
    {
        int row = tid >> 1, half = tid & 1;
        float v[32];
        const float4* src = (const float4*)(xp + (size_t)seq * 8192 + row * 64 + half * 32);
#pragma unroll
        for (int j = 0; j < 8; j++) *(float4*)&v[j * 4] = src[j];
        float s = 0.f;
#pragma unroll
        for (int j = 0; j < 32; j++) s += v[j];
        s += __shfl_xor_sync(0xffffffffu, s, 1);
        float mean = s * (1.f / 64.f);
        float vs = 0.f;
#pragma unroll
        for (int j = 0; j < 32; j++) { float d = v[j] - mean; vs += d * d; }
        vs += __shfl_xor_sync(0xffffffffu, vs, 1);
        float rstd = rsqrtf(vs * (1.f / 64.f) + EPS);
        __nv_bfloat16* dst = Asm + row * 72 + half * 32;
#pragma unroll
        for (int j = 0; j < 16; j++) {
            int c = half * 32 + 2 * j;
            float a = (v[2 * j]     - mean) * rstd * lnw[c]     + lnb[c];
            float b = (v[2 * j + 1] - mean) * rstd * lnw[c + 1] + lnb[c + 1];
            st32(dst + 2 * j, packbf2(a, b));
        }
    }
    __syncthreads();

    const int m0 = (warp & 3) * 32;
    const int nh = (warp >> 2) * 64;
    const __nv_bfloat16* Wbase = Wb;

    for (int nt = 0; nt < 7; nt++) {
        int n0 = nt * 128;
        // load W tile 128x64 bf16 (no guard: padded)
#pragma unroll
        for (int i = 0; i < 4; i++) {
            int id = i * 256 + tid;
            int row = id >> 3, j = id & 7;
            *(uint4*)(Wsm + row * 72 + j * 8) =
                *(const uint4*)(Wbase + (size_t)(n0 + row) * 64 + j * 8);
        }
        __syncthreads();

        float acc[2][8][4];
#pragma unroll
        for (int mf = 0; mf < 2; mf++)
#pragma unroll
            for (int nf = 0; nf < 8; nf++)
#pragma unroll
                for (int k = 0; k < 4; k++) acc[mf][nf][k] = 0.f;

#pragma unroll
        for (int k0 = 0; k0 < 64; k0 += 16) {
            uint32_t a[2][4];
#pragma unroll
            for (int mf = 0; mf < 2; mf++) {
                int r = m0 + mf * 16;
                a[mf][0] = ld32(Asm + (r + gID) * 72 + k0 + 2 * tig);
                a[mf][1] = ld32(Asm + (r + gID + 8) * 72 + k0 + 2 * tig);
                a[mf][2] = ld32(Asm + (r + gID) * 72 + k0 + 2 * tig + 8);
                a[mf][3] = ld32(Asm + (r + gID + 8) * 72 + k0 + 2 * tig + 8);
            }
#pragma unroll
            for (int nf = 0; nf < 8; nf++) {
                int n = nh + nf * 8;
                uint32_t b0 = ld32(Wsm + (n + gID) * 72 + k0 + 2 * tig);
                uint32_t b1 = ld32(Wsm + (n + gID) * 72 + k0 + 2 * tig + 8);
                mma_bf16(acc[0][nf], a[0][0], a[0][1], a[0][2], a[0][3], b0, b1);
                mma_bf16(acc[1][nf], a[1][0], a[1][1], a[1][2], a[1][3], b0, b1);
            }
        }

        // pack accumulators bf16 into stage (warp-disjoint regions)
#pragma unroll
        for (int mf = 0; mf < 2; mf++)
#pragma unroll
            for (int nf = 0; nf < 8; nf++) {
                int r = m0 + mf * 16, n = nh + nf * 8;
                st32(Stg + (r + gID) * 136 + n + 2 * tig,
                     packbf2(acc[mf][nf][0], acc[mf][nf][1]));
                st32(Stg + (r + gID + 8) * 136 + n + 2 * tig,
                     packbf2(acc[mf][nf][2], acc[mf][nf][3]));
            }
        __syncthreads();

        // coalesced copy stage -> zx
#pragma unroll
        for (int i = 0; i < 8; i++) {
            int id = i * 256 + tid;
            int r = id >> 4, j = id & 15;
            *(uint4*)(zxout + (size_t)(seq * 128 + r) * ZLD + n0 + j * 8) =
                *(const uint4*)(Stg + r * 136 + j * 8);
        }
        __syncthreads();
    }
}

// ---------------------------------------------------------------------------
// SSD mega-kernel, bf16 tiles, 104KB smem, 2 blocks/SM. Writes y as bf16.
// ---------------------------------------------------------------------------
__global__ __launch_bounds__(512, 2) void ssd_kernel(
    const __nv_bfloat16* __restrict__ zx, const float* __restrict__ convW,
    const float* __restrict__ convB, const float* __restrict__ dtb,
    const float* __restrict__ Al, const float* __restrict__ Dp,
    const float* __restrict__ nw, __nv_bfloat16* __restrict__ ybuf, int pi0)
{
    extern __shared__ __nv_bfloat16 pool[];
    __shared__ float Ssm[2][128];
    __shared__ float dtsm[2][128];

    __nv_bfloat16* Bs = pool + BS_OFF;
    __nv_bfloat16* Cs = pool + CS_OFF;
    __nv_bfloat16* Xt = pool + XT_OFF;
    __nv_bfloat16* G  = pool + G_OFF;

    const int blk = blockIdx.x;
    const int dir = blk & 1;
    const int seq = blk >> 1;
    const int pi  = pi0 + dir;
    const int tid = threadIdx.x;
    const int warp = tid >> 5, lane = tid & 31;
    const int gID = lane >> 2, tig = lane & 3;

    const __nv_bfloat16* zbase = zx + (size_t)seq * LSEQ * ZLD + dir * DPROJ;

    // ---- Phase 1: conv + SiLU ----
    {
        int c = tid & 255;
        int half = tid >> 8;
        int l0 = half * 64;
        const float4 w4 = *(const float4*)(convW + ((size_t)pi * CONVDIM + c) * 4);
        const float b = convB[pi * CONVDIM + c];
        const __nv_bfloat16* src = zbase + 128 + c;

        float h0 = 0.f, h1 = 0.f, h2 = 0.f;
        if (half) {
            int o1 = dir ? (127 - 61) : 61;
            int o2 = dir ? (127 - 62) : 62;
            int o3 = dir ? (127 - 63) : 63;
            h0 = __bfloat162float(src[(size_t)o1 * ZLD]);
            h1 = __bfloat162float(src[(size_t)o2 * ZLD]);
            h2 = __bfloat162float(src[(size_t)o3 * ZLD]);
        }
        __nv_bfloat16* dst;
        int dstride;
        if (c < 128)      { dst = Xt + (size_t)c * 136;  dstride = 1;  }
        else if (c < 192) { dst = Bs + (c - 128);        dstride = 72; }
        else              { dst = Cs + (c - 192);        dstride = 72; }

        for (int l = l0; l < l0 + 64; l++) {
            int orig = dir ? (127 - l) : l;
            float xin = __bfloat162float(src[(size_t)orig * ZLD]);
            float v = w4.x * h0 + w4.y * h1 + w4.z * h2 + w4.w * xin + b;
            v = v / (1.f + __expf(-v));
            dst[l * dstride] = __float2bfloat16(v);
            h0 = h1; h1 = h2; h2 = xin;
        }
    }

    // ---- Phase 2: dt softplus + cumsum ----
    if (warp < 2) {
        int h = warp;
        float aexp = __expf(Al[pi * NHEADS + h]);
        float dtbh = dtb[pi * NHEADS + h];
        float dtv[4], csum[4];
        float run = 0.f;
#pragma unroll
        for (int k = 0; k < 4; k++) {
            int l = lane * 4 + k;
            int orig = dir ? (127 - l) : l;
            float raw = __bfloat162float(zbase[(size_t)orig * ZLD + 384 + h]) + dtbh;
            float dt = (raw > 20.f) ? raw : log1pf(__expf(raw));
            run += aexp * dt;
            dtv[k] = dt; csum[k] = run;
        }
        float tot = run, scan = run;
#pragma unroll
        for (int off = 1; off < 32; off <<= 1) {
            float v = __shfl_up_sync(0xffffffffu, scan, off);
            if (lane >= off) scan += v;
        }
        float prefix = scan - tot;
#pragma unroll
        for (int k = 0; k < 4; k++) {
            int l = lane * 4 + k;
            Ssm[h][l] = prefix + csum[k];
            dtsm[h][l] = dtv[k];
        }
    }
    __syncthreads();

    // ---- Phase 3: G = C @ B^T ----
    for (int k4 = warp; k4 < 72; k4 += 16) {
        int tt = 0;
        while ((tt + 1) * (tt + 2) <= k4) tt++;
        int st = k4 - tt * (tt + 1);
        int t0 = tt * 16, s0 = st * 8;
        float acc[4] = {0.f, 0.f, 0.f, 0.f};
#pragma unroll
        for (int k0 = 0; k0 < 64; k0 += 16) {
            uint32_t a0 = ld32(Cs + (t0 + gID) * 72 + k0 + 2 * tig);
            uint32_t a1 = ld32(Cs + (t0 + gID + 8) * 72 + k0 + 2 * tig);
            uint32_t a2 = ld32(Cs + (t0 + gID) * 72 + k0 + 2 * tig + 8);
            uint32_t a3 = ld32(Cs + (t0 + gID + 8) * 72 + k0 + 2 * tig + 8);
            uint32_t b0 = ld32(Bs + (s0 + gID) * 72 + k0 + 2 * tig);
            uint32_t b1 = ld32(Bs + (s0 + gID) * 72 + k0 + 2 * tig + 8);
            mma_bf16(acc, a0, a1, a2, a3, b0, b1);
        }
        st32(G + (t0 + gID) * 136 + s0 + 2 * tig, packbf2(acc[0], acc[1]));
        st32(G + (t0 + gID + 8) * 136 + s0 + 2 * tig, packbf2(acc[2], acc[3]));
    }
    __syncthreads();

    // ---- Phase 4: Y = (G.*decay.*dt, causal) @ X ----
    {
        const int h = warp >> 3;
        const int tt = warp & 7;
        const int t0 = tt * 16;
        const int tA0 = t0 + gID, tA1 = tA0 + 8;
        const float St0 = Ssm[h][tA0], St1 = Ssm[h][tA1];

        float acc[8][4];
#pragma unroll
        for (int j = 0; j < 8; j++)
#pragma unroll
            for (int k = 0; k < 4; k++) acc[j][k] = 0.f;

        for (int ch = 0; ch <= tt; ch++) {
            int s0 = ch * 16;
            int sa = s0 + 2 * tig;
            int sb = sa + 8;
            float2 g00 = unpackbf2(ld32(G + tA0 * 136 + sa));
            float2 g10 = unpackbf2(ld32(G + tA1 * 136 + sa));
            float2 g01 = unpackbf2(ld32(G + tA0 * 136 + sb));
            float2 g11 = unpackbf2(ld32(G + tA1 * 136 + sb));
            float Sa0 = Ssm[h][sa], Sa1 = Ssm[h][sa + 1];
            float Sb0 = Ssm[h][sb], Sb1 = Ssm[h][sb + 1];
            float da0 = dtsm[h][sa], da1 = dtsm[h][sa + 1];
            float db0 = dtsm[h][sb], db1 = dtsm[h][sb + 1];
            bool diag = (ch == tt);

            float m00 = (!diag || sa     <= tA0) ? g00.x * __expf(Sa0 - St0) * da0 : 0.f;
            float m01 = (!diag || sa + 1 <= tA0) ? g00.y * __expf(Sa1 - St0) * da1 : 0.f;
            float m10 = (!diag || sa     <= tA1) ? g10.x * __expf(Sa0 - St1) * da0 : 0.f;
            float m11 = (!diag || sa + 1 <= tA1) ? g10.y * __expf(Sa1 - St1) * da1 : 0.f;
            float m20 = (!diag || sb     <= tA0) ? g01.x * __expf(Sb0 - St0) * db0 : 0.f;
            float m21 = (!diag || sb + 1 <= tA0) ? g01.y * __expf(Sb1 - St0) * db1 : 0.f;
            float m30 = (!diag || sb     <= tA1) ? g11.x * __expf(Sb0 - St1) * db0 : 0.f;
            float m31 = (!diag || sb + 1 <= tA1) ? g11.y * __expf(Sb1 - St1) * db1 : 0.f;

            uint32_t ua0 = packbf2(m00, m01);
            uint32_t ua1 = packbf2(m10, m11);
            uint32_t ua2 = packbf2(m20, m21);
            uint32_t ua3 = packbf2(m30, m31);

            const __nv_bfloat16* xb = Xt + (size_t)(h * 64 + gID) * 136;
#pragma unroll
            for (int j = 0; j < 8; j++) {
                uint32_t b0 = ld32(xb + (size_t)j * 8 * 136 + sa);
                uint32_t b1 = ld32(xb + (size_t)j * 8 * 136 + sb);
                mma_bf16(acc[j], ua0, ua1, ua2, ua3, b0, b1);
            }
        }
        __syncthreads();

#pragma unroll
        for (int j = 0; j < 8; j++) {
            int col = h * 64 + j * 8 + 2 * tig;
            st32(G + tA0 * 136 + col, packbf2(acc[j][0], acc[j][1]));
            st32(G + tA1 * 136 + col, packbf2(acc[j][2], acc[j][3]));
        }
    }
    __syncthreads();

    // ---- Phase 5: gate + RMSnorm -> bf16 y ----
    {
        float Dv0 = Dp[pi * NHEADS + 0];
        float Dv1 = Dp[pi * NHEADS + 1];
        float nw0 = nw[(size_t)pi * DINNER + lane];
        float nw1 = nw[(size_t)pi * DINNER + lane + 32];
        float nw2 = nw[(size_t)pi * DINNER + lane + 64];
        float nw3 = nw[(size_t)pi * DINNER + lane + 96];

        for (int it = 0; it < 8; it++) {
            int t = it * 16 + warp;
            int orig = dir ? (127 - t) : t;
            const __nv_bfloat16* zr = zbase + (size_t)orig * ZLD;

            float y0 = __bfloat162float(G[t * 136 + lane]);
            float y1 = __bfloat162float(G[t * 136 + lane + 32]);
            float y2 = __bfloat162float(G[t * 136 + lane + 64]);
            float y3 = __bfloat162float(G[t * 136 + lane + 96]);
            float x0 = __bfloat162float(Xt[(size_t)lane * 136 + t]);
            float x1 = __bfloat162float(Xt[(size_t)(lane + 32) * 136 + t]);
            float x2 = __bfloat162float(Xt[(size_t)(lane + 64) * 136 + t]);
            float x3 = __bfloat162float(Xt[(size_t)(lane + 96) * 136 + t]);
            float z0 = __bfloat162float(zr[lane]);
            float z1 = __bfloat162float(zr[lane + 32]);
            float z2 = __bfloat162float(zr[lane + 64]);
            float z3 = __bfloat162float(zr[lane + 96]);

            float g0 = (y0 + Dv0 * x0) * (z0 / (1.f + __expf(-z0)));
            float g1 = (y1 + Dv0 * x1) * (z1 / (1.f + __expf(-z1)));
            float g2 = (y2 + Dv1 * x2) * (z2 / (1.f + __expf(-z2)));
            float g3 = (y3 + Dv1 * x3) * (z3 / (1.f + __expf(-z3)));

            float ss = g0 * g0 + g1 * g1 + g2 * g2 + g3 * g3;
#pragma unroll
            for (int off = 16; off; off >>= 1) ss += __shfl_xor_sync(0xffffffffu, ss, off);
            float rinv = rsqrtf(ss * (1.f / 128.f) + EPS);

            __nv_bfloat16* out = ybuf + ((size_t)(seq * LSEQ + orig)) * 256 + dir * 128;
            out[lane]      = __float2bfloat16(g0 * rinv * nw0);
            out[lane + 32] = __float2bfloat16(g1 * rinv * nw1);
            out[lane + 64] = __float2bfloat16(g2 * rinv * nw2);
            out[lane + 96] = __float2bfloat16(g3 * rinv * nw3);
        }
    }
}

// ---------------------------------------------------------------------------
// Fused out-proj+fusion GEMM + bias + residual scatter-add into x.
// Block = (b,t); M-tile = 128 tokens contiguous-in-x rows for both stages.
// ---------------------------------------------------------------------------
__global__ __launch_bounds__(256) void outgemm_kernel(
    const __nv_bfloat16* __restrict__ y, const __nv_bfloat16* __restrict__ wc,
    const float* __restrict__ fb, float* __restrict__ x, int stage)
{
    extern __shared__ __nv_bfloat16 og[];
    __nv_bfloat16* Ysm = og + OG_YSM;                 // [128][72]
    __nv_bfloat16* Wsm = og + OG_WSM;                 // [64][72]
    float* Ct = (float*)((char*)og + OG_CT_B);        // [64][132]

    const int tid = threadIdx.x;
    const int warp = tid >> 5, lane = tid & 31;
    const int gID = lane >> 2, tig = lane & 3;
    const int blk = blockIdx.x;
    const int b = blk >> 7, t = blk & 127;

    const int m0 = (warp & 3) * 32;
    const int c0 = (warp >> 2) * 32;

    float acc[2][4][4];
#pragma unroll
    for (int mf = 0; mf < 2; mf++)
#pragma unroll
        for (int nf = 0; nf < 4; nf++)
#pragma unroll
            for (int k = 0; k < 4; k++) acc[mf][nf][k] = 0.f;

    for (int kt = 0; kt < 4; kt++) {
        int kb = kt * 64;
        // load y tile: 128 rows x 64 bf16
#pragma unroll
        for (int i = 0; i < 4; i++) {
            int id = i * 256 + tid;
            int m = id >> 3, j = id & 7;
            size_t token = (stage == 0) ? ((size_t)blk * 128 + m)
                                        : ((size_t)(b * 128 + m) * 128 + t);
            *(uint4*)(Ysm + m * 72 + j * 8) =
                *(const uint4*)(y + token * 256 + kb + j * 8);
        }
        // load W tile: 64 rows x 8 uint4 = 512 vector loads (2 per thread)
#pragma unroll
        for (int i = 0; i < 2; i++) {
            int id = i * 256 + tid;
            int c = id >> 3, j = id & 7;
            *(uint4*)(Wsm + c * 72 + j * 8) =
                *(const uint4*)(wc + (size_t)c * 256 + kb + j * 8);
        }
        __syncthreads();

#pragma unroll
        for (int k0 = 0; k0 < 64; k0 += 16) {
            uint32_t a[2][4];
#pragma unroll
            for (int mf = 0; mf < 2; mf++) {
                int r = m0 + mf * 16;
                a[mf][0] = ld32(Ysm + (r + gID) * 72 + k0 + 2 * tig);
                a[mf][1] = ld32(Ysm + (r + gID + 8) * 72 + k0 + 2 * tig);
                a[mf][2] = ld32(Ysm + (r + gID) * 72 + k0 + 2 * tig + 8);
                a[mf][3] = ld32(Ysm + (r + gID + 8) * 72 + k0 + 2 * tig + 8);
            }
#pragma unroll
            for (int nf = 0; nf < 4; nf++) {
                int n = c0 + nf * 8;
                uint32_t b0 = ld32(Wsm + (n + gID) * 72 + k0 + 2 * tig);
                uint32_t b1 = ld32(Wsm + (n + gID) * 72 + k0 + 2 * tig + 8);
                mma_bf16(acc[0][nf], a[0][0], a[0][1], a[0][2], a[0][3], b0, b1);
                mma_bf16(acc[1][nf], a[1][0], a[1][1], a[1][2], a[1][3], b0, b1);
            }
        }
        __syncthreads();
    }

    // transpose accumulators into Ct[c][m]
#pragma unroll
    for (int mf = 0; mf < 2; mf++)
#pragma unroll
        for (int nf = 0; nf < 4; nf++) {
            int r = m0 + mf * 16, c = c0 + nf * 8;
            Ct[(c + 2 * tig)     * 132 + r + gID]     = acc[mf][nf][0];
            Ct[(c + 2 * tig + 1) * 132 + r + gID]     = acc[mf][nf][1];
            Ct[(c + 2 * tig)     * 132 + r + gID + 8] = acc[mf][nf][2];
            Ct[(c + 2 * tig + 1) * 132 + r + gID + 8] = acc[mf][nf][3];
        }
    __syncthreads();

    // residual scatter-add: x[(b*64+c)*16384 + t*128 + m] += Ct[c][m] + fb[c]
    {
        int c = tid >> 2, q = (tid & 3) * 32;
        float bias = fb[c];
        float* xr = x + ((size_t)(b * 64 + c) * 16384 + t * 128) + q;
        const float* cr = Ct + c * 132 + q;
#pragma unroll
        for (int j = 0; j < 8; j++) {
            float4 xv = *(float4*)&xr[j * 4];
            xv.x += cr[j * 4]     + bias;
            xv.y += cr[j * 4 + 1] + bias;
            xv.z += cr[j * 4 + 2] + bias;
            xv.w += cr[j * 4 + 3] + bias;
            *(float4*)&xr[j * 4] = xv;
        }
    }
}

// ---------------------------------------------------------------------------
// Launch
// ---------------------------------------------------------------------------
extern "C" void kernel_launch(void* const* d_in, const int* in_sizes, int n_in,
                              void* d_out, int out_size)
{
    const float* x_in     = (const float*)d_in[0];
    const float* in_projW = (const float*)d_in[1];
    const float* convW    = (const float*)d_in[2];
    const float* convB    = (const float*)d_in[3];
    const float* dt_bias  = (const float*)d_in[4];
    const float* A_log    = (const float*)d_in[5];
    const float* D_param  = (const float*)d_in[6];
    const float* norm_w   = (const float*)d_in[7];
    const float* out_W    = (const float*)d_in[8];
    const float* fusion_W = (const float*)d_in[9];
    const float* fusion_b = (const float*)d_in[10];
    const float* ln_w     = (const float*)d_in[11];
    const float* ln_b     = (const float*)d_in[12];
    float* xo = (float*)d_out;

    cudaFuncSetAttribute(ssd_kernel, cudaFuncAttributeMaxDynamicSharedMemorySize, SSD_SMEM);
    cudaFuncSetAttribute(inproj_kernel, cudaFuncAttributeMaxDynamicSharedMemorySize, IP_SMEM);
    cudaFuncSetAttribute(outgemm_kernel, cudaFuncAttributeMaxDynamicSharedMemorySize, OG_SMEM);

    cudaMemcpyAsync(xo, x_in, (size_t)TOK * DMODEL * sizeof(float),
                    cudaMemcpyDeviceToDevice);

    float *p_xp;
    __nv_bfloat16 *p_zx, *p_y, *p_wbf, *p_wcomb;
    cudaGetSymbolAddress((void**)&p_xp, g_xp);
    cudaGetSymbolAddress((void**)&p_zx, g_zx);
    cudaGetSymbolAddress((void**)&p_y, g_y);
    cudaGetSymbolAddress((void**)&p_wbf, g_wbf);
    cudaGetSymbolAddress((void**)&p_wcomb, g_wcomb);

    wprep_kernel<<<2, 256>>>(in_projW, p_wbf);
    wcomb_kernel<<<2, 256>>>(out_W, fusion_W, p_wcomb);

    for (int s = 0; s < 2; s++) {
        transpose_kernel<<<NSEQ, 256>>>(xo, p_xp, s);

        inproj_kernel<<<NSEQ, 256, IP_SMEM>>>(p_xp, p_wbf + (size_t)s * WROWS * DMODEL,
                                              ln_w + s * DMODEL, ln_b + s * DMODEL, p_zx);

        ssd_kernel<<<2 * NSEQ, 512, SSD_SMEM>>>(p_zx, convW, convB, dt_bias, A_log,
                                                D_param, norm_w, p_y, 2 * s);

        outgemm_kernel<<<NSEQ, 256, OG_SMEM>>>(p_y, p_wcomb + (size_t)s * 64 * 256,
                                               fusion_b + s * DMODEL, xo, s);
    }
}

// round 16
// speedup vs baseline: 5.8208x; 1.3534x over previous
#include <cuda_runtime.h>
#include <cuda_bf16.h>
#include <mma.h>
#include <math.h>
#include <stdint.h>

// ---------------------------------------------------------------------------
// GridMambaBlock: B=4, C=64, T=128, F=128
// ---------------------------------------------------------------------------

#define TOK      65536
#define NSEQ     512
#define LSEQ     128
#define DMODEL   64
#define DINNER   128
#define NHEADS   2
#define CONVDIM  256
#define DPROJ    386
#define NPROJ2   772
#define WROWS    896          // padded combined in_proj rows per stage
#define ZLD      896          // zx row stride (bf16)
#define EPS      1e-5f

// SSD smem pool offsets (bf16 elements)
#define BS_OFF   0
#define CS_OFF   9216
#define XT_OFF   18432
#define G_OFF    35840
#define SSD_SMEM (53248 * 2)

// inproj dynamic smem (bf16 units): Asm[128][72], Wsm[128][72], Stg[128][136]
// Stg region doubles as the fp32 transpose tile (64 x 129 fp32 = 33024B <= 34816B)
#define IP_ASM   0
#define IP_WSM   9216
#define IP_STG   18432
#define IP_SMEM  ((18432 + 17408) * 2)      // 71680 B

// outgemm dynamic smem: Ysm[128][72] bf16, Wsm[64][72] bf16, Ct[64][132] fp32
#define OG_YSM   0
#define OG_WSM   9216
#define OG_CT_B  ((9216 + 4608) * 2)        // byte offset of Ct
#define OG_SMEM  (OG_CT_B + 64 * 132 * 4)   // 61440 B

// Scratch (device globals)
__device__ float g_xp[TOK * DMODEL];                   // stage-1 LN input (token-major)
__device__ __nv_bfloat16 g_zx[(size_t)TOK * ZLD];
__device__ __nv_bfloat16 g_y[(size_t)TOK * 256];
__device__ __nv_bfloat16 g_wbf[2][WROWS * DMODEL];     // in_proj W bf16, padded
__device__ __nv_bfloat16 g_wcomb[2][64 * 256];         // combined out W bf16

// ---------------------------------------------------------------------------
// helpers
// ---------------------------------------------------------------------------
__device__ __forceinline__ uint32_t packbf2(float a, float b) {
    __nv_bfloat162 t = __floats2bfloat162_rn(a, b);
    return *reinterpret_cast<uint32_t*>(&t);
}
__device__ __forceinline__ float2 unpackbf2(uint32_t u) {
    __nv_bfloat162 t = *reinterpret_cast<__nv_bfloat162*>(&u);
    return __bfloat1622float2(t);
}
__device__ __forceinline__ uint32_t ld32(const __nv_bfloat16* p) {
    return *reinterpret_cast<const uint32_t*>(p);
}
__device__ __forceinline__ void st32(__nv_bfloat16* p, uint32_t v) {
    *reinterpret_cast<uint32_t*>(p) = v;
}
__device__ __forceinline__ void mma_bf16(float* c, uint32_t a0, uint32_t a1,
                                         uint32_t a2, uint32_t a3,
                                         uint32_t b0, uint32_t b1) {
    asm volatile(
        "mma.sync.aligned.m16n8k16.row.col.f32.bf16.bf16.f32 "
        "{%0,%1,%2,%3}, {%4,%5,%6,%7}, {%8,%9}, {%0,%1,%2,%3};\n"
        : "+f"(c[0]), "+f"(c[1]), "+f"(c[2]), "+f"(c[3])
        : "r"(a0), "r"(a1), "r"(a2), "r"(a3), "r"(b0), "r"(b1));
}

// ---------------------------------------------------------------------------
// Weight prep: in_proj -> bf16 padded [2][896][64]
// ---------------------------------------------------------------------------
__global__ void wprep_kernel(const float* __restrict__ W, __nv_bfloat16* __restrict__ wb)
{
    int s = blockIdx.x;
    for (int idx = threadIdx.x; idx < WROWS * DMODEL; idx += blockDim.x) {
        int row = idx >> 6, c = idx & 63;
        float v = 0.f;
        if (row < NPROJ2) {
            int pi = 2 * s + (row >= DPROJ);
            int r = (row >= DPROJ) ? row - DPROJ : row;
            v = W[((size_t)pi * DPROJ + r) * DMODEL + c];
        }
        wb[(size_t)s * WROWS * DMODEL + idx] = __float2bfloat16(v);
    }
}

// ---------------------------------------------------------------------------
// Combined out_proj+fusion weights -> bf16
// ---------------------------------------------------------------------------
__global__ void wcomb_kernel(const float* __restrict__ outW,
                             const float* __restrict__ fusW,
                             __nv_bfloat16* __restrict__ wc)
{
    int s = blockIdx.x;
    for (int idx = threadIdx.x; idx < 64 * 256; idx += blockDim.x) {
        int n = idx >> 8, k = idx & 255;
        int d = k >> 7, c = k & 127;
        const float* wf = fusW + (size_t)(s * 64 + n) * 128 + d * 64;
        const float* wo = outW + (size_t)((s * 2 + d) * 64) * 128 + c;
        float acc = 0.f;
#pragma unroll
        for (int j = 0; j < 64; j++) acc += wf[j] * wo[(size_t)j * 128];
        wc[(size_t)s * 64 * 256 + idx] = __float2bfloat16(acc);
    }
}

// ---------------------------------------------------------------------------
// Fused (transpose +) LayerNorm + in_proj (bf16 raw mma) -> bf16 zx.
// Block = seq, 256 threads. stage0: read x (B,C,T,F) with in-smem transpose;
// else read token-major xp.
// ---------------------------------------------------------------------------
__global__ __launch_bounds__(256) void inproj_kernel(
    const float* __restrict__ xsrc, const __nv_bfloat16* __restrict__ Wb,
    const float* __restrict__ lnw, const float* __restrict__ lnb,
    __nv_bfloat16* __restrict__ zxout, int stage0)
{
    extern __shared__ __nv_bfloat16 ip[];
    __nv_bfloat16* Asm = ip + IP_ASM;   // [128][72]
    __nv_bfloat16* Wsm = ip + IP_WSM;   // [128][72]
    __nv_bfloat16* Stg = ip + IP_STG;   // [128][136] (also fp32 Tile 64x129)
    float* Tile = (float*)(ip + IP_STG);

    const int tid = threadIdx.x;
    const int warp = tid >> 5, lane = tid & 31;
    const int gID = lane >> 2, tig = lane & 3;
    const int seq = blockIdx.x;

    if (stage0) {
        // load x slice [c][f] for fixed (b,t) -> Tile (coalesced on f)
        int b = seq >> 7, t = seq & 127;
        const float* src = xsrc + ((size_t)b * 64) * 16384 + t * 128;
#pragma unroll
        for (int i = 0; i < 32; i++) {
            int id = i * 256 + tid;
            int c = id >> 7, f = id & 127;
            Tile[c * 129 + f] = src[(size_t)c * 16384 + f];
        }
        __syncthreads();
    }

    // ---- LayerNorm (2 threads per row) -> Asm bf16 ----
    {
        int row = tid >> 1, half = tid & 1;
        float v[32];
        if (stage0) {
#pragma unroll
            for (int j = 0; j < 32; j++) v[j] = Tile[(half * 32 + j) * 129 + row];
        } else {
            const float4* src = (const float4*)(xsrc + (size_t)seq * 8192 + row * 64 + half * 32);
#pragma unroll
            for (int j = 0; j < 8; j++) *(float4*)&v[j * 4] = src[j];
        }
        float s = 0.f;
#pragma unroll
        for (int j = 0; j < 32; j++) s += v[j];
        s += __shfl_xor_sync(0xffffffffu, s, 1);
        float mean = s * (1.f / 64.f);
        float vs = 0.f;
#pragma unroll
        for (int j = 0; j < 32; j++) { float d = v[j] - mean; vs += d * d; }
        vs += __shfl_xor_sync(0xffffffffu, vs, 1);
        float rstd = rsqrtf(vs * (1.f / 64.f) + EPS);
        __nv_bfloat16* dst = Asm + row * 72 + half * 32;
#pragma unroll
        for (int j = 0; j < 16; j++) {
            int c = half * 32 + 2 * j;
            float a = (v[2 * j]     - mean) * rstd * lnw[c]     + lnb[c];
            float b = (v[2 * j + 1] - mean) * rstd * lnw[c + 1] + lnb[c + 1];
            st32(dst + 2 * j, packbf2(a, b));
        }
    }
    __syncthreads();

    const int m0 = (warp & 3) * 32;
    const int nh = (warp >> 2) * 64;

    for (int nt = 0; nt < 7; nt++) {
        int n0 = nt * 128;
#pragma unroll
        for (int i = 0; i < 4; i++) {
            int id = i * 256 + tid;
            int row = id >> 3, j = id & 7;
            *(uint4*)(Wsm + row * 72 + j * 8) =
                *(const uint4*)(Wb + (size_t)(n0 + row) * 64 + j * 8);
        }
        __syncthreads();

        float acc[2][8][4];
#pragma unroll
        for (int mf = 0; mf < 2; mf++)
#pragma unroll
            for (int nf = 0; nf < 8; nf++)
#pragma unroll
                for (int k = 0; k < 4; k++) acc[mf][nf][k] = 0.f;

#pragma unroll
        for (int k0 = 0; k0 < 64; k0 += 16) {
            uint32_t a[2][4];
#pragma unroll
            for (int mf = 0; mf < 2; mf++) {
                int r = m0 + mf * 16;
                a[mf][0] = ld32(Asm + (r + gID) * 72 + k0 + 2 * tig);
                a[mf][1] = ld32(Asm + (r + gID + 8) * 72 + k0 + 2 * tig);
                a[mf][2] = ld32(Asm + (r + gID) * 72 + k0 + 2 * tig + 8);
                a[mf][3] = ld32(Asm + (r + gID + 8) * 72 + k0 + 2 * tig + 8);
            }
#pragma unroll
            for (int nf = 0; nf < 8; nf++) {
                int n = nh + nf * 8;
                uint32_t b0 = ld32(Wsm + (n + gID) * 72 + k0 + 2 * tig);
                uint32_t b1 = ld32(Wsm + (n + gID) * 72 + k0 + 2 * tig + 8);
                mma_bf16(acc[0][nf], a[0][0], a[0][1], a[0][2], a[0][3], b0, b1);
                mma_bf16(acc[1][nf], a[1][0], a[1][1], a[1][2], a[1][3], b0, b1);
            }
        }

#pragma unroll
        for (int mf = 0; mf < 2; mf++)
#pragma unroll
            for (int nf = 0; nf < 8; nf++) {
                int r = m0 + mf * 16, n = nh + nf * 8;
                st32(Stg + (r + gID) * 136 + n + 2 * tig,
                     packbf2(acc[mf][nf][0], acc[mf][nf][1]));
                st32(Stg + (r + gID + 8) * 136 + n + 2 * tig,
                     packbf2(acc[mf][nf][2], acc[mf][nf][3]));
            }
        __syncthreads();

#pragma unroll
        for (int i = 0; i < 8; i++) {
            int id = i * 256 + tid;
            int r = id >> 4, j = id & 15;
            *(uint4*)(zxout + (size_t)(seq * 128 + r) * ZLD + n0 + j * 8) =
                *(const uint4*)(Stg + r * 136 + j * 8);
        }
        __syncthreads();
    }
}

// ---------------------------------------------------------------------------
// SSD mega-kernel, bf16 tiles, 104KB smem, 2 blocks/SM. Writes y as bf16.
// ---------------------------------------------------------------------------
__global__ __launch_bounds__(512, 2) void ssd_kernel(
    const __nv_bfloat16* __restrict__ zx, const float* __restrict__ convW,
    const float* __restrict__ convB, const float* __restrict__ dtb,
    const float* __restrict__ Al, const float* __restrict__ Dp,
    const float* __restrict__ nw, __nv_bfloat16* __restrict__ ybuf, int pi0)
{
    extern __shared__ __nv_bfloat16 pool[];
    __shared__ float Ssm[2][128];
    __shared__ float dtsm[2][128];

    __nv_bfloat16* Bs = pool + BS_OFF;
    __nv_bfloat16* Cs = pool + CS_OFF;
    __nv_bfloat16* Xt = pool + XT_OFF;
    __nv_bfloat16* G  = pool + G_OFF;

    const int blk = blockIdx.x;
    const int dir = blk & 1;
    const int seq = blk >> 1;
    const int pi  = pi0 + dir;
    const int tid = threadIdx.x;
    const int warp = tid >> 5, lane = tid & 31;
    const int gID = lane >> 2, tig = lane & 3;

    const __nv_bfloat16* zbase = zx + (size_t)seq * LSEQ * ZLD + dir * DPROJ;
    const intptr_t zstep = dir ? -(intptr_t)ZLD : (intptr_t)ZLD;

    // ---- Phase 1: conv + SiLU, 8-wide load batches for MLP ----
    {
        int c = tid & 255;
        int half = tid >> 8;
        int l0 = half * 64;
        const float4 w4 = *(const float4*)(convW + ((size_t)pi * CONVDIM + c) * 4);
        const float b = convB[pi * CONVDIM + c];
        const __nv_bfloat16* src = zbase + 128 + c;
        // pointer to orig(l0) position
        const __nv_bfloat16* sp = src + (intptr_t)(dir ? (127 - l0) : l0) * ZLD;

        float h0 = 0.f, h1 = 0.f, h2 = 0.f;
        if (half) {
            h0 = __bfloat162float(sp[-3 * zstep]);
            h1 = __bfloat162float(sp[-2 * zstep]);
            h2 = __bfloat162float(sp[-1 * zstep]);
        }
        __nv_bfloat16* dst;
        int dstride;
        if (c < 128)      { dst = Xt + (size_t)c * 136 + l0; dstride = 1;  }
        else if (c < 192) { dst = Bs + (c - 128) + l0 * 72;  dstride = 72; }
        else              { dst = Cs + (c - 192) + l0 * 72;  dstride = 72; }

        for (int lb = 0; lb < 64; lb += 8) {
            float xv[8];
#pragma unroll
            for (int k = 0; k < 8; k++)
                xv[k] = __bfloat162float(sp[(intptr_t)(lb + k) * zstep]);
#pragma unroll
            for (int k = 0; k < 8; k++) {
                float v = w4.x * h0 + w4.y * h1 + w4.z * h2 + w4.w * xv[k] + b;
                v = v / (1.f + __expf(-v));
                dst[(lb + k) * dstride] = __float2bfloat16(v);
                h0 = h1; h1 = h2; h2 = xv[k];
            }
        }
    }

    // ---- Phase 2: dt softplus + cumsum ----
    if (warp < 2) {
        int h = warp;
        float aexp = __expf(Al[pi * NHEADS + h]);
        float dtbh = dtb[pi * NHEADS + h];
        float dtv[4], csum[4];
        float run = 0.f;
        const __nv_bfloat16* dp = zbase + 384 + h +
            (intptr_t)(dir ? (127 - lane * 4) : (lane * 4)) * ZLD;
#pragma unroll
        for (int k = 0; k < 4; k++) {
            float raw = __bfloat162float(dp[(intptr_t)k * zstep]) + dtbh;
            float dt = (raw > 20.f) ? raw : log1pf(__expf(raw));
            run += aexp * dt;
            dtv[k] = dt; csum[k] = run;
        }
        float tot = run, scan = run;
#pragma unroll
        for (int off = 1; off < 32; off <<= 1) {
            float v = __shfl_up_sync(0xffffffffu, scan, off);
            if (lane >= off) scan += v;
        }
        float prefix = scan - tot;
#pragma unroll
        for (int k = 0; k < 4; k++) {
            int l = lane * 4 + k;
            Ssm[h][l] = prefix + csum[k];
            dtsm[h][l] = dtv[k];
        }
    }
    __syncthreads();

    // ---- Phase 3: G = C @ B^T ----
    for (int k4 = warp; k4 < 72; k4 += 16) {
        int tt = 0;
        while ((tt + 1) * (tt + 2) <= k4) tt++;
        int st = k4 - tt * (tt + 1);
        int t0 = tt * 16, s0 = st * 8;
        float acc[4] = {0.f, 0.f, 0.f, 0.f};
#pragma unroll
        for (int k0 = 0; k0 < 64; k0 += 16) {
            uint32_t a0 = ld32(Cs + (t0 + gID) * 72 + k0 + 2 * tig);
            uint32_t a1 = ld32(Cs + (t0 + gID + 8) * 72 + k0 + 2 * tig);
            uint32_t a2 = ld32(Cs + (t0 + gID) * 72 + k0 + 2 * tig + 8);
            uint32_t a3 = ld32(Cs + (t0 + gID + 8) * 72 + k0 + 2 * tig + 8);
            uint32_t b0 = ld32(Bs + (s0 + gID) * 72 + k0 + 2 * tig);
            uint32_t b1 = ld32(Bs + (s0 + gID) * 72 + k0 + 2 * tig + 8);
            mma_bf16(acc, a0, a1, a2, a3, b0, b1);
        }
        st32(G + (t0 + gID) * 136 + s0 + 2 * tig, packbf2(acc[0], acc[1]));
        st32(G + (t0 + gID + 8) * 136 + s0 + 2 * tig, packbf2(acc[2], acc[3]));
    }
    __syncthreads();

    // ---- Phase 4: Y = (G.*decay.*dt, causal) @ X ----
    {
        const int h = warp >> 3;
        const int tt = warp & 7;
        const int t0 = tt * 16;
        const int tA0 = t0 + gID, tA1 = tA0 + 8;
        const float St0 = Ssm[h][tA0], St1 = Ssm[h][tA1];

        float acc[8][4];
#pragma unroll
        for (int j = 0; j < 8; j++)
#pragma unroll
            for (int k = 0; k < 4; k++) acc[j][k] = 0.f;

        for (int ch = 0; ch <= tt; ch++) {
            int s0 = ch * 16;
            int sa = s0 + 2 * tig;
            int sb = sa + 8;
            float2 g00 = unpackbf2(ld32(G + tA0 * 136 + sa));
            float2 g10 = unpackbf2(ld32(G + tA1 * 136 + sa));
            float2 g01 = unpackbf2(ld32(G + tA0 * 136 + sb));
            float2 g11 = unpackbf2(ld32(G + tA1 * 136 + sb));
            float Sa0 = Ssm[h][sa], Sa1 = Ssm[h][sa + 1];
            float Sb0 = Ssm[h][sb], Sb1 = Ssm[h][sb + 1];
            float da0 = dtsm[h][sa], da1 = dtsm[h][sa + 1];
            float db0 = dtsm[h][sb], db1 = dtsm[h][sb + 1];
            bool diag = (ch == tt);

            float m00 = (!diag || sa     <= tA0) ? g00.x * __expf(Sa0 - St0) * da0 : 0.f;
            float m01 = (!diag || sa + 1 <= tA0) ? g00.y * __expf(Sa1 - St0) * da1 : 0.f;
            float m10 = (!diag || sa     <= tA1) ? g10.x * __expf(Sa0 - St1) * da0 : 0.f;
            float m11 = (!diag || sa + 1 <= tA1) ? g10.y * __expf(Sa1 - St1) * da1 : 0.f;
            float m20 = (!diag || sb     <= tA0) ? g01.x * __expf(Sb0 - St0) * db0 : 0.f;
            float m21 = (!diag || sb + 1 <= tA0) ? g01.y * __expf(Sb1 - St0) * db1 : 0.f;
            float m30 = (!diag || sb     <= tA1) ? g11.x * __expf(Sb0 - St1) * db0 : 0.f;
            float m31 = (!diag || sb + 1 <= tA1) ? g11.y * __expf(Sb1 - St1) * db1 : 0.f;

            uint32_t ua0 = packbf2(m00, m01);
            uint32_t ua1 = packbf2(m10, m11);
            uint32_t ua2 = packbf2(m20, m21);
            uint32_t ua3 = packbf2(m30, m31);

            const __nv_bfloat16* xb = Xt + (size_t)(h * 64 + gID) * 136;
#pragma unroll
            for (int j = 0; j < 8; j++) {
                uint32_t b0 = ld32(xb + (size_t)j * 8 * 136 + sa);
                uint32_t b1 = ld32(xb + (size_t)j * 8 * 136 + sb);
                mma_bf16(acc[j], ua0, ua1, ua2, ua3, b0, b1);
            }
        }
        __syncthreads();

#pragma unroll
        for (int j = 0; j < 8; j++) {
            int col = h * 64 + j * 8 + 2 * tig;
            st32(G + tA0 * 136 + col, packbf2(acc[j][0], acc[j][1]));
            st32(G + tA1 * 136 + col, packbf2(acc[j][2], acc[j][3]));
        }
    }
    __syncthreads();

    // ---- Phase 5: gate + RMSnorm -> bf16 y ----
    {
        float Dv0 = Dp[pi * NHEADS + 0];
        float Dv1 = Dp[pi * NHEADS + 1];
        float nw0 = nw[(size_t)pi * DINNER + lane];
        float nw1 = nw[(size_t)pi * DINNER + lane + 32];
        float nw2 = nw[(size_t)pi * DINNER + lane + 64];
        float nw3 = nw[(size_t)pi * DINNER + lane + 96];

        for (int it = 0; it < 8; it++) {
            int t = it * 16 + warp;
            int orig = dir ? (127 - t) : t;
            const __nv_bfloat16* zr = zbase + (size_t)orig * ZLD;
            // issue z loads early
            float z0 = __bfloat162float(zr[lane]);
            float z1 = __bfloat162float(zr[lane + 32]);
            float z2 = __bfloat162float(zr[lane + 64]);
            float z3 = __bfloat162float(zr[lane + 96]);

            float y0 = __bfloat162float(G[t * 136 + lane]);
            float y1 = __bfloat162float(G[t * 136 + lane + 32]);
            float y2 = __bfloat162float(G[t * 136 + lane + 64]);
            float y3 = __bfloat162float(G[t * 136 + lane + 96]);
            float x0 = __bfloat162float(Xt[(size_t)lane * 136 + t]);
            float x1 = __bfloat162float(Xt[(size_t)(lane + 32) * 136 + t]);
            float x2 = __bfloat162float(Xt[(size_t)(lane + 64) * 136 + t]);
            float x3 = __bfloat162float(Xt[(size_t)(lane + 96) * 136 + t]);

            float g0 = (y0 + Dv0 * x0) * (z0 / (1.f + __expf(-z0)));
            float g1 = (y1 + Dv0 * x1) * (z1 / (1.f + __expf(-z1)));
            float g2 = (y2 + Dv1 * x2) * (z2 / (1.f + __expf(-z2)));
            float g3 = (y3 + Dv1 * x3) * (z3 / (1.f + __expf(-z3)));

            float ss = g0 * g0 + g1 * g1 + g2 * g2 + g3 * g3;
#pragma unroll
            for (int off = 16; off; off >>= 1) ss += __shfl_xor_sync(0xffffffffu, ss, off);
            float rinv = rsqrtf(ss * (1.f / 128.f) + EPS);

            __nv_bfloat16* out = ybuf + ((size_t)(seq * LSEQ + orig)) * 256 + dir * 128;
            out[lane]      = __float2bfloat16(g0 * rinv * nw0);
            out[lane + 32] = __float2bfloat16(g1 * rinv * nw1);
            out[lane + 64] = __float2bfloat16(g2 * rinv * nw2);
            out[lane + 96] = __float2bfloat16(g3 * rinv * nw3);
        }
    }
}

// ---------------------------------------------------------------------------
// Fused out-proj+fusion GEMM + bias + residual add.
// Reads residual from xin, writes updated residual to xout (may alias xin).
// If xp_out != null (stage 0): also writes updated values token-major for
// stage-1 LN input.
// ---------------------------------------------------------------------------
__global__ __launch_bounds__(256) void outgemm_kernel(
    const __nv_bfloat16* __restrict__ y, const __nv_bfloat16* __restrict__ wc,
    const float* __restrict__ fb, const float* __restrict__ xin,
    float* __restrict__ xout, float* __restrict__ xp_out, int stage)
{
    extern __shared__ __nv_bfloat16 og[];
    __nv_bfloat16* Ysm = og + OG_YSM;                 // [128][72]
    __nv_bfloat16* Wsm = og + OG_WSM;                 // [64][72]
    float* Ct = (float*)((char*)og + OG_CT_B);        // [64][132]

    const int tid = threadIdx.x;
    const int warp = tid >> 5, lane = tid & 31;
    const int gID = lane >> 2, tig = lane & 3;
    const int blk = blockIdx.x;
    const int b = blk >> 7, t = blk & 127;

    const int m0 = (warp & 3) * 32;
    const int c0 = (warp >> 2) * 32;

    float acc[2][4][4];
#pragma unroll
    for (int mf = 0; mf < 2; mf++)
#pragma unroll
        for (int nf = 0; nf < 4; nf++)
#pragma unroll
            for (int k = 0; k < 4; k++) acc[mf][nf][k] = 0.f;

    for (int kt = 0; kt < 4; kt++) {
        int kb = kt * 64;
#pragma unroll
        for (int i = 0; i < 4; i++) {
            int id = i * 256 + tid;
            int m = id >> 3, j = id & 7;
            size_t token = (stage == 0) ? ((size_t)blk * 128 + m)
                                        : ((size_t)(b * 128 + m) * 128 + t);
            *(uint4*)(Ysm + m * 72 + j * 8) =
                *(const uint4*)(y + token * 256 + kb + j * 8);
        }
#pragma unroll
        for (int i = 0; i < 2; i++) {
            int id = i * 256 + tid;
            int c = id >> 3, j = id & 7;
            *(uint4*)(Wsm + c * 72 + j * 8) =
                *(const uint4*)(wc + (size_t)c * 256 + kb + j * 8);
        }
        __syncthreads();

#pragma unroll
        for (int k0 = 0; k0 < 64; k0 += 16) {
            uint32_t a[2][4];
#pragma unroll
            for (int mf = 0; mf < 2; mf++) {
                int r = m0 + mf * 16;
                a[mf][0] = ld32(Ysm + (r + gID) * 72 + k0 + 2 * tig);
                a[mf][1] = ld32(Ysm + (r + gID + 8) * 72 + k0 + 2 * tig);
                a[mf][2] = ld32(Ysm + (r + gID) * 72 + k0 + 2 * tig + 8);
                a[mf][3] = ld32(Ysm + (r + gID + 8) * 72 + k0 + 2 * tig + 8);
            }
#pragma unroll
            for (int nf = 0; nf < 4; nf++) {
                int n = c0 + nf * 8;
                uint32_t b0 = ld32(Wsm + (n + gID) * 72 + k0 + 2 * tig);
                uint32_t b1 = ld32(Wsm + (n + gID) * 72 + k0 + 2 * tig + 8);
                mma_bf16(acc[0][nf], a[0][0], a[0][1], a[0][2], a[0][3], b0, b1);
                mma_bf16(acc[1][nf], a[1][0], a[1][1], a[1][2], a[1][3], b0, b1);
            }
        }
        __syncthreads();
    }

    // transpose accumulators into Ct[c][m]
#pragma unroll
    for (int mf = 0; mf < 2; mf++)
#pragma unroll
        for (int nf = 0; nf < 4; nf++) {
            int r = m0 + mf * 16, c = c0 + nf * 8;
            Ct[(c + 2 * tig)     * 132 + r + gID]     = acc[mf][nf][0];
            Ct[(c + 2 * tig + 1) * 132 + r + gID]     = acc[mf][nf][1];
            Ct[(c + 2 * tig)     * 132 + r + gID + 8] = acc[mf][nf][2];
            Ct[(c + 2 * tig + 1) * 132 + r + gID + 8] = acc[mf][nf][3];
        }
    __syncthreads();

    // residual: xout[...] = xin[...] + Ct + bias; store updated value into Ct
    {
        int c = tid >> 2, q = (tid & 3) * 32;
        float bias = fb[c];
        size_t off = ((size_t)(b * 64 + c) * 16384 + t * 128) + q;
        const float* xr = xin + off;
        float* xw = xout + off;
        float* cr = Ct + c * 132 + q;
#pragma unroll
        for (int j = 0; j < 8; j++) {
            float4 xv = *(const float4*)&xr[j * 4];
            xv.x += cr[j * 4]     + bias;
            xv.y += cr[j * 4 + 1] + bias;
            xv.z += cr[j * 4 + 2] + bias;
            xv.w += cr[j * 4 + 3] + bias;
            *(float4*)&xw[j * 4] = xv;
            cr[j * 4]     = xv.x;
            cr[j * 4 + 1] = xv.y;
            cr[j * 4 + 2] = xv.z;
            cr[j * 4 + 3] = xv.w;
        }
    }

    if (xp_out) {
        __syncthreads();
        // stage-1 token for element (c, f=m) is (b*128+m)*128+t
        float* base = xp_out + ((size_t)(b * 16384 + t)) * 64;
#pragma unroll
        for (int i = 0; i < 32; i++) {
            int id = i * 256 + tid;
            int m = id >> 6, c = id & 63;
            base[(size_t)m * 8192 + c] = Ct[c * 132 + m];
        }
    }
}

// ---------------------------------------------------------------------------
// Launch
// ---------------------------------------------------------------------------
extern "C" void kernel_launch(void* const* d_in, const int* in_sizes, int n_in,
                              void* d_out, int out_size)
{
    const float* x_in     = (const float*)d_in[0];
    const float* in_projW = (const float*)d_in[1];
    const float* convW    = (const float*)d_in[2];
    const float* convB    = (const float*)d_in[3];
    const float* dt_bias  = (const float*)d_in[4];
    const float* A_log    = (const float*)d_in[5];
    const float* D_param  = (const float*)d_in[6];
    const float* norm_w   = (const float*)d_in[7];
    const float* out_W    = (const float*)d_in[8];
    const float* fusion_W = (const float*)d_in[9];
    const float* fusion_b = (const float*)d_in[10];
    const float* ln_w     = (const float*)d_in[11];
    const float* ln_b     = (const float*)d_in[12];
    float* xo = (float*)d_out;

    cudaFuncSetAttribute(ssd_kernel, cudaFuncAttributeMaxDynamicSharedMemorySize, SSD_SMEM);
    cudaFuncSetAttribute(inproj_kernel, cudaFuncAttributeMaxDynamicSharedMemorySize, IP_SMEM);
    cudaFuncSetAttribute(outgemm_kernel, cudaFuncAttributeMaxDynamicSharedMemorySize, OG_SMEM);

    float *p_xp;
    __nv_bfloat16 *p_zx, *p_y, *p_wbf, *p_wcomb;
    cudaGetSymbolAddress((void**)&p_xp, g_xp);
    cudaGetSymbolAddress((void**)&p_zx, g_zx);
    cudaGetSymbolAddress((void**)&p_y, g_y);
    cudaGetSymbolAddress((void**)&p_wbf, g_wbf);
    cudaGetSymbolAddress((void**)&p_wcomb, g_wcomb);

    wprep_kernel<<<2, 256>>>(in_projW, p_wbf);
    wcomb_kernel<<<2, 256>>>(out_W, fusion_W, p_wcomb);

    // ---- stage 0: read x_in directly; outgemm writes xo fresh + xp for s1 ----
    inproj_kernel<<<NSEQ, 256, IP_SMEM>>>(x_in, p_wbf, ln_w, ln_b, p_zx, 1);
    ssd_kernel<<<2 * NSEQ, 512, SSD_SMEM>>>(p_zx, convW, convB, dt_bias, A_log,
                                            D_param, norm_w, p_y, 0);
    outgemm_kernel<<<NSEQ, 256, OG_SMEM>>>(p_y, p_wcomb, fusion_b, x_in, xo, p_xp, 0);

    // ---- stage 1: LN input from xp (token-major); in-place residual on xo ----
    inproj_kernel<<<NSEQ, 256, IP_SMEM>>>(p_xp, p_wbf + (size_t)WROWS * DMODEL,
                                          ln_w + DMODEL, ln_b + DMODEL, p_zx, 0);
    ssd_kernel<<<2 * NSEQ, 512, SSD_SMEM>>>(p_zx, convW, convB, dt_bias, A_log,
                                            D_param, norm_w, p_y, 2);
    outgemm_kernel<<<NSEQ, 256, OG_SMEM>>>(p_y, p_wcomb + (size_t)64 * 256,
                                           fusion_b + DMODEL, xo, xo, nullptr, 1);
}